// round 15
// baseline (speedup 1.0000x reference)
#include <cuda_runtime.h>
#include <cuda_bf16.h>
#include <math.h>
#include <stdint.h>

#define N_NODES  20000
#define N_EDGES  320000
#define N_GRAPHS 1000

// ---------------- static device scratch (no allocations allowed) ----------------
__device__ float    g_xl[N_NODES * 256];
__device__ float    g_xr[N_NODES * 256];
__device__ uint16_t g_ahi[N_NODES * 256];
__device__ uint16_t g_alo[N_NODES * 256];
__device__ uint16_t g_whL[256 * 256];
__device__ uint16_t g_wlL[256 * 256];
__device__ uint16_t g_whR[256 * 256];
__device__ uint16_t g_wlR[256 * 256];
__device__ int      g_deg[N_NODES];
__device__ int      g_rowptr[N_NODES + 1];
__device__ int      g_cursor[N_NODES];
__device__ int      g_csr_src[N_EDGES];
__device__ float4   g_csr_ea[N_EDGES];
__device__ float    g_sums[N_GRAPHS * 64];
__device__ int      g_cnt[N_GRAPHS];

// ---------------- utility kernels ----------------
__global__ void zero_i32(int* p, int n) {
    int i = blockIdx.x * blockDim.x + threadIdx.x;
    if (i < n) p[i] = 0;
}
__global__ void zero_f32(float* p, int n) {
    int i = blockIdx.x * blockDim.x + threadIdx.x;
    if (i < n) p[i] = 0.f;
}
__global__ void hist_k(const int* __restrict__ dst, int* __restrict__ deg) {
    int e = blockIdx.x * blockDim.x + threadIdx.x;
    if (e < N_EDGES) atomicAdd(&deg[dst[e]], 1);
}

__global__ void scan_k(const int* __restrict__ deg, int* __restrict__ rowptr,
                       int* __restrict__ cursor) {
    __shared__ int sh[1024];
    const int CH = 20;
    int t = threadIdx.x;
    int base = t * CH;
    int loc[CH];
    int s = 0;
    #pragma unroll
    for (int i = 0; i < CH; i++) {
        int idx = base + i;
        int v = (idx < N_NODES) ? deg[idx] : 0;
        loc[i] = s;
        s += v;
    }
    sh[t] = s;
    __syncthreads();
    for (int off = 1; off < 1024; off <<= 1) {
        int v = (t >= off) ? sh[t - off] : 0;
        __syncthreads();
        sh[t] += v;
        __syncthreads();
    }
    int pre = (t > 0) ? sh[t - 1] : 0;
    #pragma unroll
    for (int i = 0; i < CH; i++) {
        int idx = base + i;
        if (idx < N_NODES) {
            int v = pre + loc[i];
            rowptr[idx] = v;
            cursor[idx] = v;
        }
    }
    if (t == 1023) rowptr[N_NODES] = sh[1023];
}

__global__ void scatter_k(const int* __restrict__ src, const int* __restrict__ dst,
                          const float4* __restrict__ ea, int* __restrict__ cursor,
                          int* __restrict__ csr_src, float4* __restrict__ csr_ea) {
    int e = blockIdx.x * blockDim.x + threadIdx.x;
    if (e < N_EDGES) {
        int p = atomicAdd(&cursor[dst[e]], 1);
        csr_src[p] = src[e];
        csr_ea[p] = ea[e];
    }
}

// dual W split: both L and R weights, W[K][Nc] fp32 -> transposed [Nc][K] bf16 hi/lo
__global__ void splitW_dual(const float* __restrict__ WL, const float* __restrict__ WR,
                            __nv_bfloat16* __restrict__ hiL, __nv_bfloat16* __restrict__ loL,
                            __nv_bfloat16* __restrict__ hiR, __nv_bfloat16* __restrict__ loR,
                            int K, int Nc) {
    int i = blockIdx.x * blockDim.x + threadIdx.x;
    if (i < K * Nc) {
        int k = i / Nc, n = i - k * Nc;
        float v = WL[i];
        __nv_bfloat16 h = __float2bfloat16(v);
        hiL[(size_t)n * K + k] = h;
        loL[(size_t)n * K + k] = __float2bfloat16(v - __bfloat162float(h));
        v = WR[i];
        h = __float2bfloat16(v);
        hiR[(size_t)n * K + k] = h;
        loR[(size_t)n * K + k] = __float2bfloat16(v - __bfloat162float(h));
    }
}

// ---------------- layer-1 dual GEMM (K=12 -> 256 for both Wl and Wr) ----------------
__global__ void gemm_k12_dual(const float* __restrict__ x,
                              const float* __restrict__ WL, const float* __restrict__ bL,
                              const float* __restrict__ WR, const float* __restrict__ bR,
                              float* __restrict__ xl, float* __restrict__ xr) {
    __shared__ float WsL[12 * 256];
    __shared__ float WsR[12 * 256];
    __shared__ float xs[32 * 12];
    int tid = threadIdx.x;
    int r0 = blockIdx.x * 32;
    for (int i = tid; i < 12 * 256; i += 256) {
        WsL[i] = WL[i];
        WsR[i] = WR[i];
    }
    for (int i = tid; i < 32 * 12; i += 256) {
        int r = r0 + i / 12;
        xs[i] = (r < N_NODES) ? x[(size_t)r * 12 + (i % 12)] : 0.f;
    }
    __syncthreads();
    float bbL = bL[tid], bbR = bR[tid];
    for (int r = 0; r < 32; r++) {
        int gr = r0 + r;
        if (gr >= N_NODES) break;
        float accL = bbL, accR = bbR;
        #pragma unroll
        for (int k = 0; k < 12; k++) {
            float xv = xs[r * 12 + k];
            accL += xv * WsL[k * 256 + tid];
            accR += xv * WsR[k * 256 + tid];
        }
        xl[(size_t)gr * 256 + tid] = accL;
        xr[(size_t)gr * 256 + tid] = accR;
    }
}

// ---------------- bf16 mma.sync GEMM with pre-split hi/lo (3-term) ----------------
// Dual variant: blockIdx.z selects (B, bias, C) operand set; A shared.
// Register-staged double buffering: next chunk's global loads overlap compute.
__device__ __forceinline__ uint32_t smem_u32(const void* p) {
    uint32_t a;
    asm("{ .reg .u64 t; cvta.to.shared.u64 t, %1; cvt.u32.u64 %0, t; }" : "=r"(a) : "l"(p));
    return a;
}
#define LDSM_X4(r0, r1, r2, r3, addr) \
    asm volatile("ldmatrix.sync.aligned.m8n8.x4.shared.b16 {%0,%1,%2,%3}, [%4];" \
                 : "=r"(r0), "=r"(r1), "=r"(r2), "=r"(r3) : "r"(addr))
#define LDSM_X2(r0, r1, addr) \
    asm volatile("ldmatrix.sync.aligned.m8n8.x2.shared.b16 {%0,%1}, [%2];" \
                 : "=r"(r0), "=r"(r1) : "r"(addr))
__device__ __forceinline__ void mma_bf16(float* d, uint32_t a0, uint32_t a1,
                                         uint32_t a2, uint32_t a3,
                                         uint32_t b0, uint32_t b1) {
    asm volatile(
        "mma.sync.aligned.m16n8k16.row.col.f32.bf16.bf16.f32 "
        "{%0,%1,%2,%3},{%4,%5,%6,%7},{%8,%9},{%0,%1,%2,%3};"
        : "+f"(d[0]), "+f"(d[1]), "+f"(d[2]), "+f"(d[3])
        : "r"(a0), "r"(a1), "r"(a2), "r"(a3), "r"(b0), "r"(b1));
}

__global__ __launch_bounds__(256) void gemm_bf16_dual(
    const __nv_bfloat16* __restrict__ Ahi, const __nv_bfloat16* __restrict__ Alo,
    const __nv_bfloat16* __restrict__ BhiL, const __nv_bfloat16* __restrict__ BloL,
    const __nv_bfloat16* __restrict__ BhiR, const __nv_bfloat16* __restrict__ BloR,
    const float* __restrict__ biasL, const float* __restrict__ biasR,
    float* __restrict__ CL, float* __restrict__ CR, int M, int K, int Ncols) {
    const int SA = 40;
    __shared__ __align__(16) uint16_t As_h[128 * 40];
    __shared__ __align__(16) uint16_t As_l[128 * 40];
    __shared__ __align__(16) uint16_t Bs_h[64 * 40];
    __shared__ __align__(16) uint16_t Bs_l[64 * 40];

    const __nv_bfloat16* BhiT = blockIdx.z ? BhiR : BhiL;
    const __nv_bfloat16* BloT = blockIdx.z ? BloR : BloL;
    const float* bias = blockIdx.z ? biasR : biasL;
    float* C = blockIdx.z ? CR : CL;

    int tid = threadIdx.x, lane = tid & 31, warp = tid >> 5;
    int warpM = warp & 3, warpN = warp >> 2;
    int row0 = blockIdx.y * 128, col0 = blockIdx.x * 64;

    float acc[2][4][4];
    #pragma unroll
    for (int mt = 0; mt < 2; mt++)
        #pragma unroll
        for (int nt = 0; nt < 4; nt++)
            #pragma unroll
            for (int i = 0; i < 4; i++) acc[mt][nt][i] = 0.f;

    uint32_t aadH[2], aadL[2], badH[4], badL[4];
    {
        int ar = (lane & 7) + ((lane >> 3) & 1) * 8;
        int ac = (lane >> 4) * 8;
        #pragma unroll
        for (int mt = 0; mt < 2; mt++) {
            int r = warpM * 32 + mt * 16 + ar;
            aadH[mt] = smem_u32(As_h) + (uint32_t)(r * SA + ac) * 2;
            aadL[mt] = smem_u32(As_l) + (uint32_t)(r * SA + ac) * 2;
        }
        int l16 = lane & 15;
        int bn = l16 & 7;
        int bc = ((l16 >> 3) & 1) * 8;
        #pragma unroll
        for (int nt = 0; nt < 4; nt++) {
            int n = warpN * 32 + nt * 8 + bn;
            badH[nt] = smem_u32(Bs_h) + (uint32_t)(n * SA + bc) * 2;
            badL[nt] = smem_u32(Bs_l) + (uint32_t)(n * SA + bc) * 2;
        }
    }

    // per-thread staging indices
    int a_r0 = tid >> 2, a_sk0 = (tid & 3) * 8;          // iter 0
    int a_r1 = (tid + 256) >> 2, a_sk1 = (tid & 3) * 8;  // iter 1
    int b_r = tid >> 2, b_sk = (tid & 3) * 8;

    // preload chunk 0 into registers
    uint4 pAh0, pAl0, pAh1, pAl1, pBh, pBl;
    {
        pAh0 = make_uint4(0, 0, 0, 0); pAl0 = pAh0; pAh1 = pAh0; pAl1 = pAh0;
        int g0 = row0 + a_r0;
        if (g0 < M) {
            size_t off = (size_t)g0 * K + a_sk0;
            pAh0 = *(const uint4*)(Ahi + off);
            pAl0 = *(const uint4*)(Alo + off);
        }
        int g1 = row0 + a_r1;
        if (g1 < M) {
            size_t off = (size_t)g1 * K + a_sk1;
            pAh1 = *(const uint4*)(Ahi + off);
            pAl1 = *(const uint4*)(Alo + off);
        }
        size_t boff = (size_t)(col0 + b_r) * K + b_sk;
        pBh = *(const uint4*)(BhiT + boff);
        pBl = *(const uint4*)(BloT + boff);
    }

    for (int k0 = 0; k0 < K; k0 += 32) {
        // store staged chunk to smem
        *(uint4*)&As_h[a_r0 * SA + a_sk0] = pAh0;
        *(uint4*)&As_l[a_r0 * SA + a_sk0] = pAl0;
        *(uint4*)&As_h[a_r1 * SA + a_sk1] = pAh1;
        *(uint4*)&As_l[a_r1 * SA + a_sk1] = pAl1;
        *(uint4*)&Bs_h[b_r * SA + b_sk] = pBh;
        *(uint4*)&Bs_l[b_r * SA + b_sk] = pBl;
        __syncthreads();

        // preload next chunk (overlaps with compute below)
        int kn = k0 + 32;
        if (kn < K) {
            pAh0 = make_uint4(0, 0, 0, 0); pAl0 = pAh0; pAh1 = pAh0; pAl1 = pAh0;
            int g0 = row0 + a_r0;
            if (g0 < M) {
                size_t off = (size_t)g0 * K + kn + a_sk0;
                pAh0 = *(const uint4*)(Ahi + off);
                pAl0 = *(const uint4*)(Alo + off);
            }
            int g1 = row0 + a_r1;
            if (g1 < M) {
                size_t off = (size_t)g1 * K + kn + a_sk1;
                pAh1 = *(const uint4*)(Ahi + off);
                pAl1 = *(const uint4*)(Alo + off);
            }
            size_t boff = (size_t)(col0 + b_r) * K + kn + b_sk;
            pBh = *(const uint4*)(BhiT + boff);
            pBl = *(const uint4*)(BloT + boff);
        }

        #pragma unroll
        for (int ks = 0; ks < 32; ks += 16) {
            uint32_t kb = ks * 2;
            uint32_t ah[2][4], al[2][4], bh[4][2], bl[4][2];
            #pragma unroll
            for (int mt = 0; mt < 2; mt++) {
                LDSM_X4(ah[mt][0], ah[mt][1], ah[mt][2], ah[mt][3], aadH[mt] + kb);
                LDSM_X4(al[mt][0], al[mt][1], al[mt][2], al[mt][3], aadL[mt] + kb);
            }
            #pragma unroll
            for (int nt = 0; nt < 4; nt++) {
                LDSM_X2(bh[nt][0], bh[nt][1], badH[nt] + kb);
                LDSM_X2(bl[nt][0], bl[nt][1], badL[nt] + kb);
            }
            #pragma unroll
            for (int mt = 0; mt < 2; mt++)
                #pragma unroll
                for (int nt = 0; nt < 4; nt++) {
                    mma_bf16(acc[mt][nt], ah[mt][0], ah[mt][1], ah[mt][2], ah[mt][3],
                             bl[nt][0], bl[nt][1]);
                    mma_bf16(acc[mt][nt], al[mt][0], al[mt][1], al[mt][2], al[mt][3],
                             bh[nt][0], bh[nt][1]);
                    mma_bf16(acc[mt][nt], ah[mt][0], ah[mt][1], ah[mt][2], ah[mt][3],
                             bh[nt][0], bh[nt][1]);
                }
        }
        __syncthreads();
    }

    int g = lane >> 2, tg = lane & 3;
    #pragma unroll
    for (int nt = 0; nt < 4; nt++) {
        int col = col0 + warpN * 32 + nt * 8 + 2 * tg;
        float2 bv = *(const float2*)(bias + col);
        #pragma unroll
        for (int mt = 0; mt < 2; mt++) {
            int r = row0 + warpM * 32 + mt * 16 + g;
            if (r < M) {
                float2 v = make_float2(acc[mt][nt][0] + bv.x, acc[mt][nt][1] + bv.y);
                *(float2*)(C + (size_t)r * Ncols + col) = v;
            }
            if (r + 8 < M) {
                float2 v = make_float2(acc[mt][nt][2] + bv.x, acc[mt][nt][3] + bv.y);
                *(float2*)(C + (size_t)(r + 8) * Ncols + col) = v;
            }
        }
    }
}

// ---------------- fused edge aggregation, H=4: ONE warp per node (R13 config) ------
// lane owns 8 contiguous channels; per-head 3-SHFL butterfly. 2-edge stages with
// full value+index rotation.
__global__ void edge_agg_h4(const int* __restrict__ rowptr, const int* __restrict__ csr_src,
                            const float4* __restrict__ csr_ea,
                            const float* __restrict__ xl, const float* __restrict__ xr,
                            const float* __restrict__ We, const float* __restrict__ att,
                            const float* __restrict__ bias,
                            __nv_bfloat16* __restrict__ out_hi,
                            __nv_bfloat16* __restrict__ out_lo) {
    int w = (blockIdx.x * blockDim.x + threadIdx.x) >> 5;  // node
    int lane = threadIdx.x & 31;
    if (w >= N_NODES) return;
    int n = w;
    int c = lane * 8;

    float xrv[8], atv[8], wev[4][8];
    {
        float4 v0 = *(const float4*)(xr + (size_t)n * 256 + c);
        float4 v1 = *(const float4*)(xr + (size_t)n * 256 + c + 4);
        xrv[0] = v0.x; xrv[1] = v0.y; xrv[2] = v0.z; xrv[3] = v0.w;
        xrv[4] = v1.x; xrv[5] = v1.y; xrv[6] = v1.z; xrv[7] = v1.w;
        v0 = *(const float4*)(att + c);
        v1 = *(const float4*)(att + c + 4);
        atv[0] = v0.x; atv[1] = v0.y; atv[2] = v0.z; atv[3] = v0.w;
        atv[4] = v1.x; atv[5] = v1.y; atv[6] = v1.z; atv[7] = v1.w;
        #pragma unroll
        for (int f = 0; f < 4; f++) {
            v0 = *(const float4*)(We + f * 256 + c);
            v1 = *(const float4*)(We + f * 256 + c + 4);
            wev[f][0] = v0.x; wev[f][1] = v0.y; wev[f][2] = v0.z; wev[f][3] = v0.w;
            wev[f][4] = v1.x; wev[f][5] = v1.y; wev[f][6] = v1.z; wev[f][7] = v1.w;
        }
    }

    float s = 0.f, a[8];
    #pragma unroll
    for (int j = 0; j < 8; j++) a[j] = 0.f;
    int beg = rowptr[n], end = rowptr[n + 1];

    float4 ce0 = make_float4(0, 0, 0, 0), ce1 = ce0;
    float4 xa0 = ce0, xb0 = ce0, xa1 = ce0, xb1 = ce0;
    if (beg + 1 < end) {
        int s0i = csr_src[beg], s1i = csr_src[beg + 1];
        ce0 = csr_ea[beg];
        ce1 = csr_ea[beg + 1];
        xa0 = *(const float4*)(xl + (size_t)s0i * 256 + c);
        xb0 = *(const float4*)(xl + (size_t)s0i * 256 + c + 4);
        xa1 = *(const float4*)(xl + (size_t)s1i * 256 + c);
        xb1 = *(const float4*)(xl + (size_t)s1i * 256 + c + 4);
    }

    int i = beg;
    for (; i + 1 < end; i += 2) {
        float4 ne0 = ce0, ne1 = ce1, nxa0 = xa0, nxb0 = xb0, nxa1 = xa1, nxb1 = xb1;
        if (i + 3 < end) {
            int s0i = csr_src[i + 2], s1i = csr_src[i + 3];
            ne0 = csr_ea[i + 2];
            ne1 = csr_ea[i + 3];
            nxa0 = *(const float4*)(xl + (size_t)s0i * 256 + c);
            nxb0 = *(const float4*)(xl + (size_t)s0i * 256 + c + 4);
            nxa1 = *(const float4*)(xl + (size_t)s1i * 256 + c);
            nxb1 = *(const float4*)(xl + (size_t)s1i * 256 + c + 4);
        }

        float x0[8] = {xa0.x, xa0.y, xa0.z, xa0.w, xb0.x, xb0.y, xb0.z, xb0.w};
        float x1[8] = {xa1.x, xa1.y, xa1.z, xa1.w, xb1.x, xb1.y, xb1.z, xb1.w};
        float t0 = 0.f, t1 = 0.f;
        #pragma unroll
        for (int j = 0; j < 8; j++) {
            float z0 = x0[j] + xrv[j] + ce0.x * wev[0][j] + ce0.y * wev[1][j]
                       + ce0.z * wev[2][j] + ce0.w * wev[3][j];
            float z1 = x1[j] + xrv[j] + ce1.x * wev[0][j] + ce1.y * wev[1][j]
                       + ce1.z * wev[2][j] + ce1.w * wev[3][j];
            z0 = z0 > 0.f ? z0 : 0.2f * z0;
            z1 = z1 > 0.f ? z1 : 0.2f * z1;
            t0 += z0 * atv[j];
            t1 += z1 * atv[j];
        }
        #pragma unroll
        for (int o = 4; o > 0; o >>= 1) {
            t0 += __shfl_xor_sync(0xFFFFFFFFu, t0, o);
            t1 += __shfl_xor_sync(0xFFFFFFFFu, t1, o);
        }
        float p0 = __expf(t0), p1 = __expf(t1);
        s += p0 + p1;
        #pragma unroll
        for (int j = 0; j < 8; j++) a[j] += p0 * x0[j] + p1 * x1[j];

        ce0 = ne0; ce1 = ne1;
        xa0 = nxa0; xb0 = nxb0; xa1 = nxa1; xb1 = nxb1;
    }
    if (i < end) {
        int sn = csr_src[i];
        float4 eav = csr_ea[i];
        float4 xa = *(const float4*)(xl + (size_t)sn * 256 + c);
        float4 xb = *(const float4*)(xl + (size_t)sn * 256 + c + 4);
        float xv[8] = {xa.x, xa.y, xa.z, xa.w, xb.x, xb.y, xb.z, xb.w};
        float t = 0.f;
        #pragma unroll
        for (int j = 0; j < 8; j++) {
            float z = xv[j] + xrv[j] + eav.x * wev[0][j] + eav.y * wev[1][j]
                      + eav.z * wev[2][j] + eav.w * wev[3][j];
            z = z > 0.f ? z : 0.2f * z;
            t += z * atv[j];
        }
        #pragma unroll
        for (int o = 4; o > 0; o >>= 1) t += __shfl_xor_sync(0xFFFFFFFFu, t, o);
        float p = __expf(t);
        s += p;
        #pragma unroll
        for (int j = 0; j < 8; j++) a[j] += p * xv[j];
    }

    float inv = 1.f / (s + 1e-16f);
    float4 bv0 = *(const float4*)(bias + c);
    float4 bv1 = *(const float4*)(bias + c + 4);
    float bb[8] = {bv0.x, bv0.y, bv0.z, bv0.w, bv1.x, bv1.y, bv1.z, bv1.w};
    uint16_t hv[8], lv[8];
    #pragma unroll
    for (int j = 0; j < 8; j++) {
        float r = a[j] * inv + bb[j];
        r = r > 0.f ? r : expm1f(r);   // ELU
        __nv_bfloat16 h = __float2bfloat16(r);
        __nv_bfloat16 l = __float2bfloat16(r - __bfloat162float(h));
        hv[j] = *(uint16_t*)&h;
        lv[j] = *(uint16_t*)&l;
    }
    *(uint4*)(out_hi + (size_t)n * 256 + c) = *(uint4*)hv;
    *(uint4*)(out_lo + (size_t)n * 256 + c) = *(uint4*)lv;
}

// ---------------- edge aggregation, H=1 (layer 3) + fused global-mean-pool --------
__global__ void edge_agg_h1_pool(const int* __restrict__ rowptr, const int* __restrict__ csr_src,
                                 const float4* __restrict__ csr_ea,
                                 const float* __restrict__ xl, const float* __restrict__ xr,
                                 const float* __restrict__ We, const float* __restrict__ att,
                                 const float* __restrict__ bias, const int* __restrict__ batch,
                                 float* __restrict__ sums, int* __restrict__ cnt) {
    const int D = 64;
    int w = (blockIdx.x * blockDim.x + threadIdx.x) >> 5;
    int lane = threadIdx.x & 31;
    int n = w;
    if (n >= N_NODES) return;

    int c = 2 * lane;
    float2 xrv = *(const float2*)(xr + (size_t)n * D + c);
    float2 atv = *(const float2*)(att + c);
    float2 wev[4];
    #pragma unroll
    for (int f = 0; f < 4; f++) wev[f] = *(const float2*)(We + f * D + c);

    float s0 = 0.f, a00 = 0.f, a01 = 0.f;
    float s1 = 0.f, a10 = 0.f, a11 = 0.f;
    int beg = rowptr[n], end = rowptr[n + 1];

    int i = beg;
    for (; i + 3 < end; i += 4) {
        int sn0 = csr_src[i], sn1 = csr_src[i + 1], sn2 = csr_src[i + 2], sn3 = csr_src[i + 3];
        float4 e0 = csr_ea[i], e1 = csr_ea[i + 1], e2 = csr_ea[i + 2], e3 = csr_ea[i + 3];
        float2 x0 = *(const float2*)(xl + (size_t)sn0 * D + c);
        float2 x1 = *(const float2*)(xl + (size_t)sn1 * D + c);
        float2 x2 = *(const float2*)(xl + (size_t)sn2 * D + c);
        float2 x3 = *(const float2*)(xl + (size_t)sn3 * D + c);

        float za, zb, t0, t1, t2, t3;
        za = x0.x + xrv.x + e0.x * wev[0].x + e0.y * wev[1].x + e0.z * wev[2].x + e0.w * wev[3].x;
        zb = x0.y + xrv.y + e0.x * wev[0].y + e0.y * wev[1].y + e0.z * wev[2].y + e0.w * wev[3].y;
        za = za > 0.f ? za : 0.2f * za; zb = zb > 0.f ? zb : 0.2f * zb;
        t0 = za * atv.x + zb * atv.y;
        za = x1.x + xrv.x + e1.x * wev[0].x + e1.y * wev[1].x + e1.z * wev[2].x + e1.w * wev[3].x;
        zb = x1.y + xrv.y + e1.x * wev[0].y + e1.y * wev[1].y + e1.z * wev[2].y + e1.w * wev[3].y;
        za = za > 0.f ? za : 0.2f * za; zb = zb > 0.f ? zb : 0.2f * zb;
        t1 = za * atv.x + zb * atv.y;
        za = x2.x + xrv.x + e2.x * wev[0].x + e2.y * wev[1].x + e2.z * wev[2].x + e2.w * wev[3].x;
        zb = x2.y + xrv.y + e2.x * wev[0].y + e2.y * wev[1].y + e2.z * wev[2].y + e2.w * wev[3].y;
        za = za > 0.f ? za : 0.2f * za; zb = zb > 0.f ? zb : 0.2f * zb;
        t2 = za * atv.x + zb * atv.y;
        za = x3.x + xrv.x + e3.x * wev[0].x + e3.y * wev[1].x + e3.z * wev[2].x + e3.w * wev[3].x;
        zb = x3.y + xrv.y + e3.x * wev[0].y + e3.y * wev[1].y + e3.z * wev[2].y + e3.w * wev[3].y;
        za = za > 0.f ? za : 0.2f * za; zb = zb > 0.f ? zb : 0.2f * zb;
        t3 = za * atv.x + zb * atv.y;

        #pragma unroll
        for (int o = 16; o > 0; o >>= 1) {
            t0 += __shfl_xor_sync(0xFFFFFFFFu, t0, o);
            t1 += __shfl_xor_sync(0xFFFFFFFFu, t1, o);
            t2 += __shfl_xor_sync(0xFFFFFFFFu, t2, o);
            t3 += __shfl_xor_sync(0xFFFFFFFFu, t3, o);
        }
        float p0 = __expf(t0), p1 = __expf(t1), p2 = __expf(t2), p3 = __expf(t3);
        s0 += p0; a00 += p0 * x0.x; a01 += p0 * x0.y;
        s1 += p1; a10 += p1 * x1.x; a11 += p1 * x1.y;
        s0 += p2; a00 += p2 * x2.x; a01 += p2 * x2.y;
        s1 += p3; a10 += p3 * x3.x; a11 += p3 * x3.y;
    }
    for (; i < end; i++) {
        int sn = csr_src[i];
        float4 eav = csr_ea[i];
        float2 xv = *(const float2*)(xl + (size_t)sn * D + c);
        float z0 = xv.x + xrv.x + eav.x * wev[0].x + eav.y * wev[1].x + eav.z * wev[2].x + eav.w * wev[3].x;
        float z1 = xv.y + xrv.y + eav.x * wev[0].y + eav.y * wev[1].y + eav.z * wev[2].y + eav.w * wev[3].y;
        z0 = z0 > 0.f ? z0 : 0.2f * z0;
        z1 = z1 > 0.f ? z1 : 0.2f * z1;
        float t = z0 * atv.x + z1 * atv.y;
        #pragma unroll
        for (int o = 16; o > 0; o >>= 1) t += __shfl_xor_sync(0xFFFFFFFFu, t, o);
        float p = __expf(t);
        s0 += p; a00 += p * xv.x; a01 += p * xv.y;
    }
    float s = s0 + s1;
    float a0 = a00 + a10;
    float a1 = a01 + a11;

    float inv = 1.f / (s + 1e-16f);
    float2 bv = *(const float2*)(bias + c);
    float r0 = a0 * inv + bv.x;
    float r1 = a1 * inv + bv.y;

    int g = batch[n];
    atomicAdd(&sums[g * 64 + c], r0);
    atomicAdd(&sums[g * 64 + c + 1], r1);
    if (lane == 0) atomicAdd(&cnt[g], 1);
}

// ---------------- MLP head ----------------
__global__ void mlp_k(const float* __restrict__ sums, const int* __restrict__ cnt,
                      const float* __restrict__ mW1, const float* __restrict__ mb1,
                      const float* __restrict__ mW2, const float* __restrict__ mb2,
                      const float* __restrict__ mW3, const float* __restrict__ mb3,
                      float* __restrict__ out) {
    __shared__ float gv[64];
    __shared__ float h1[32];
    __shared__ float h2[16];
    int g = blockIdx.x, t = threadIdx.x;
    float cf = fmaxf((float)cnt[g], 1.f);
    gv[t] = sums[g * 64 + t] / cf;
    __syncthreads();
    if (t < 32) {
        float a = mb1[t];
        #pragma unroll
        for (int k = 0; k < 64; k++) a += gv[k] * mW1[k * 32 + t];
        h1[t] = fmaxf(a, 0.f);
    }
    __syncthreads();
    if (t < 16) {
        float a = mb2[t];
        #pragma unroll
        for (int k = 0; k < 32; k++) a += h1[k] * mW2[k * 16 + t];
        h2[t] = fmaxf(a, 0.f);
    }
    __syncthreads();
    if (t < 4) {
        float a = mb3[t];
        #pragma unroll
        for (int k = 0; k < 16; k++) a += h2[k] * mW3[k * 4 + t];
        out[g * 4 + t] = a;
    }
}

// ---------------- launch ----------------
extern "C" void kernel_launch(void* const* d_in, const int* in_sizes, int n_in,
                              void* d_out, int out_size) {
    (void)in_sizes; (void)n_in; (void)out_size;
    const float* x     = (const float*)d_in[0];
    const int*   ei    = (const int*)d_in[1];
    const float* ea    = (const float*)d_in[2];
    const int*   batch = (const int*)d_in[3];
    const float* Wl1 = (const float*)d_in[4],  *bl1 = (const float*)d_in[5];
    const float* Wr1 = (const float*)d_in[6],  *br1 = (const float*)d_in[7];
    const float* We1 = (const float*)d_in[8],  *att1 = (const float*)d_in[9],  *bias1 = (const float*)d_in[10];
    const float* Wl2 = (const float*)d_in[11], *bl2 = (const float*)d_in[12];
    const float* Wr2 = (const float*)d_in[13], *br2 = (const float*)d_in[14];
    const float* We2 = (const float*)d_in[15], *att2 = (const float*)d_in[16], *bias2 = (const float*)d_in[17];
    const float* Wl3 = (const float*)d_in[18], *bl3 = (const float*)d_in[19];
    const float* Wr3 = (const float*)d_in[20], *br3 = (const float*)d_in[21];
    const float* We3 = (const float*)d_in[22], *att3 = (const float*)d_in[23], *bias3 = (const float*)d_in[24];
    const float* mW1 = (const float*)d_in[25], *mb1 = (const float*)d_in[26];
    const float* mW2 = (const float*)d_in[27], *mb2 = (const float*)d_in[28];
    const float* mW3 = (const float*)d_in[29], *mb3 = (const float*)d_in[30];
    float* out = (float*)d_out;

    const int* srcp = ei;
    const int* dstp = ei + N_EDGES;

    float *xl, *xr, *sums;
    int *deg, *rowptr, *cursor, *csr_src, *cnt;
    float4* csr_ea;
    __nv_bfloat16 *ahi, *alo, *whL, *wlL, *whR, *wlR;
    cudaGetSymbolAddress((void**)&xl, g_xl);
    cudaGetSymbolAddress((void**)&xr, g_xr);
    cudaGetSymbolAddress((void**)&sums, g_sums);
    cudaGetSymbolAddress((void**)&deg, g_deg);
    cudaGetSymbolAddress((void**)&rowptr, g_rowptr);
    cudaGetSymbolAddress((void**)&cursor, g_cursor);
    cudaGetSymbolAddress((void**)&csr_src, g_csr_src);
    cudaGetSymbolAddress((void**)&csr_ea, g_csr_ea);
    cudaGetSymbolAddress((void**)&cnt, g_cnt);
    cudaGetSymbolAddress((void**)&ahi, g_ahi);
    cudaGetSymbolAddress((void**)&alo, g_alo);
    cudaGetSymbolAddress((void**)&whL, g_whL);
    cudaGetSymbolAddress((void**)&wlL, g_wlL);
    cudaGetSymbolAddress((void**)&whR, g_whR);
    cudaGetSymbolAddress((void**)&wlR, g_wlR);

    // CSR by destination (shared by all 3 layers)
    zero_i32<<<(N_NODES + 255) / 256, 256>>>(deg, N_NODES);
    hist_k<<<(N_EDGES + 255) / 256, 256>>>(dstp, deg);
    scan_k<<<1, 1024>>>(deg, rowptr, cursor);
    scatter_k<<<(N_EDGES + 255) / 256, 256>>>(srcp, dstp, (const float4*)ea, cursor, csr_src, csr_ea);

    // layer-1 dual GEMM (xl + xr in one pass)
    gemm_k12_dual<<<(N_NODES + 31) / 32, 256>>>(x, Wl1, bl1, Wr1, br1, xl, xr);

    edge_agg_h4<<<2500, 256>>>(rowptr, csr_src, csr_ea, xl, xr, We1, att1, bias1, ahi, alo);

    // ---- layer 2 (256 -> 256, H=4): one dual launch for L+R ----
    splitW_dual<<<(256 * 256 + 255) / 256, 256>>>(Wl2, Wr2, whL, wlL, whR, wlR, 256, 256);
    gemm_bf16_dual<<<dim3(4, 157, 2), 256>>>(ahi, alo, whL, wlL, whR, wlR, bl2, br2,
                                             xl, xr, N_NODES, 256, 256);
    edge_agg_h4<<<2500, 256>>>(rowptr, csr_src, csr_ea, xl, xr, We2, att2, bias2, ahi, alo);

    // ---- layer 3 (256 -> 64, H=1, no ELU), pool fused into epilogue ----
    splitW_dual<<<(256 * 64 + 255) / 256, 256>>>(Wl3, Wr3, whL, wlL, whR, wlR, 256, 64);
    gemm_bf16_dual<<<dim3(1, 157, 2), 256>>>(ahi, alo, whL, wlL, whR, wlR, bl3, br3,
                                             xl, xr, N_NODES, 256, 64);
    zero_f32<<<(N_GRAPHS * 64 + 255) / 256, 256>>>(sums, N_GRAPHS * 64);
    zero_i32<<<(N_GRAPHS + 255) / 256, 256>>>(cnt, N_GRAPHS);
    edge_agg_h1_pool<<<2500, 256>>>(rowptr, csr_src, csr_ea, xl, xr, We3, att3, bias3,
                                    batch, sums, cnt);

    // ---- MLP head ----
    mlp_k<<<N_GRAPHS, 64>>>(sums, cnt, mW1, mb1, mW2, mb2, mW3, mb3, out);
}

// round 16
// speedup vs baseline: 1.0147x; 1.0147x over previous
#include <cuda_runtime.h>
#include <cuda_bf16.h>
#include <math.h>
#include <stdint.h>

#define N_NODES  20000
#define N_EDGES  320000
#define N_GRAPHS 1000

typedef unsigned long long ull;

// ---------------- static device scratch (no allocations allowed) ----------------
__device__ float    g_xl[N_NODES * 256];
__device__ float    g_xr[N_NODES * 256];
__device__ uint16_t g_ahi[N_NODES * 256];
__device__ uint16_t g_alo[N_NODES * 256];
__device__ uint16_t g_whL[256 * 256];
__device__ uint16_t g_wlL[256 * 256];
__device__ uint16_t g_whR[256 * 256];
__device__ uint16_t g_wlR[256 * 256];
__device__ int      g_deg[N_NODES];
__device__ int      g_rowptr[N_NODES + 1];
__device__ int      g_cursor[N_NODES];
__device__ int      g_csr_src[N_EDGES];
__device__ float4   g_csr_ea[N_EDGES];
__device__ float    g_sums[N_GRAPHS * 64];
__device__ int      g_cnt[N_GRAPHS];

// ---------------- packed f32x2 helpers (base-Blackwell PTX, not 'a'-gated) --------
__device__ __forceinline__ ull pk2(float lo, float hi) {
    ull r;
    asm("mov.b64 %0, {%1, %2};" : "=l"(r) : "f"(lo), "f"(hi));
    return r;
}
__device__ __forceinline__ void upk2(float& lo, float& hi, ull v) {
    asm("mov.b64 {%0, %1}, %2;" : "=f"(lo), "=f"(hi) : "l"(v));
}
__device__ __forceinline__ ull add2(ull a, ull b) {
    ull r;
    asm("add.rn.f32x2 %0, %1, %2;" : "=l"(r) : "l"(a), "l"(b));
    return r;
}
__device__ __forceinline__ ull fma2(ull a, ull b, ull c) {
    ull r;
    asm("fma.rn.f32x2 %0, %1, %2, %3;" : "=l"(r) : "l"(a), "l"(b), "l"(c));
    return r;
}

// ---------------- utility kernels ----------------
__global__ void zero_i32(int* p, int n) {
    int i = blockIdx.x * blockDim.x + threadIdx.x;
    if (i < n) p[i] = 0;
}
__global__ void zero_f32(float* p, int n) {
    int i = blockIdx.x * blockDim.x + threadIdx.x;
    if (i < n) p[i] = 0.f;
}
__global__ void hist_k(const int* __restrict__ dst, int* __restrict__ deg) {
    int e = blockIdx.x * blockDim.x + threadIdx.x;
    if (e < N_EDGES) atomicAdd(&deg[dst[e]], 1);
}

__global__ void scan_k(const int* __restrict__ deg, int* __restrict__ rowptr,
                       int* __restrict__ cursor) {
    __shared__ int sh[1024];
    const int CH = 20;
    int t = threadIdx.x;
    int base = t * CH;
    int loc[CH];
    int s = 0;
    #pragma unroll
    for (int i = 0; i < CH; i++) {
        int idx = base + i;
        int v = (idx < N_NODES) ? deg[idx] : 0;
        loc[i] = s;
        s += v;
    }
    sh[t] = s;
    __syncthreads();
    for (int off = 1; off < 1024; off <<= 1) {
        int v = (t >= off) ? sh[t - off] : 0;
        __syncthreads();
        sh[t] += v;
        __syncthreads();
    }
    int pre = (t > 0) ? sh[t - 1] : 0;
    #pragma unroll
    for (int i = 0; i < CH; i++) {
        int idx = base + i;
        if (idx < N_NODES) {
            int v = pre + loc[i];
            rowptr[idx] = v;
            cursor[idx] = v;
        }
    }
    if (t == 1023) rowptr[N_NODES] = sh[1023];
}

__global__ void scatter_k(const int* __restrict__ src, const int* __restrict__ dst,
                          const float4* __restrict__ ea, int* __restrict__ cursor,
                          int* __restrict__ csr_src, float4* __restrict__ csr_ea) {
    int e = blockIdx.x * blockDim.x + threadIdx.x;
    if (e < N_EDGES) {
        int p = atomicAdd(&cursor[dst[e]], 1);
        csr_src[p] = src[e];
        csr_ea[p] = ea[e];
    }
}

// dual W split: both L and R weights, W[K][Nc] fp32 -> transposed [Nc][K] bf16 hi/lo
__global__ void splitW_dual(const float* __restrict__ WL, const float* __restrict__ WR,
                            __nv_bfloat16* __restrict__ hiL, __nv_bfloat16* __restrict__ loL,
                            __nv_bfloat16* __restrict__ hiR, __nv_bfloat16* __restrict__ loR,
                            int K, int Nc) {
    int i = blockIdx.x * blockDim.x + threadIdx.x;
    if (i < K * Nc) {
        int k = i / Nc, n = i - k * Nc;
        float v = WL[i];
        __nv_bfloat16 h = __float2bfloat16(v);
        hiL[(size_t)n * K + k] = h;
        loL[(size_t)n * K + k] = __float2bfloat16(v - __bfloat162float(h));
        v = WR[i];
        h = __float2bfloat16(v);
        hiR[(size_t)n * K + k] = h;
        loR[(size_t)n * K + k] = __float2bfloat16(v - __bfloat162float(h));
    }
}

// ---------------- layer-1 dual GEMM (K=12 -> 256 for both Wl and Wr) ----------------
__global__ void gemm_k12_dual(const float* __restrict__ x,
                              const float* __restrict__ WL, const float* __restrict__ bL,
                              const float* __restrict__ WR, const float* __restrict__ bR,
                              float* __restrict__ xl, float* __restrict__ xr) {
    __shared__ float WsL[12 * 256];
    __shared__ float WsR[12 * 256];
    __shared__ float xs[32 * 12];
    int tid = threadIdx.x;
    int r0 = blockIdx.x * 32;
    for (int i = tid; i < 12 * 256; i += 256) {
        WsL[i] = WL[i];
        WsR[i] = WR[i];
    }
    for (int i = tid; i < 32 * 12; i += 256) {
        int r = r0 + i / 12;
        xs[i] = (r < N_NODES) ? x[(size_t)r * 12 + (i % 12)] : 0.f;
    }
    __syncthreads();
    float bbL = bL[tid], bbR = bR[tid];
    for (int r = 0; r < 32; r++) {
        int gr = r0 + r;
        if (gr >= N_NODES) break;
        float accL = bbL, accR = bbR;
        #pragma unroll
        for (int k = 0; k < 12; k++) {
            float xv = xs[r * 12 + k];
            accL += xv * WsL[k * 256 + tid];
            accR += xv * WsR[k * 256 + tid];
        }
        xl[(size_t)gr * 256 + tid] = accL;
        xr[(size_t)gr * 256 + tid] = accR;
    }
}

// ---------------- bf16 mma.sync GEMM with pre-split hi/lo (3-term), R13 version ----
__device__ __forceinline__ uint32_t smem_u32(const void* p) {
    uint32_t a;
    asm("{ .reg .u64 t; cvta.to.shared.u64 t, %1; cvt.u32.u64 %0, t; }" : "=r"(a) : "l"(p));
    return a;
}
#define LDSM_X4(r0, r1, r2, r3, addr) \
    asm volatile("ldmatrix.sync.aligned.m8n8.x4.shared.b16 {%0,%1,%2,%3}, [%4];" \
                 : "=r"(r0), "=r"(r1), "=r"(r2), "=r"(r3) : "r"(addr))
#define LDSM_X2(r0, r1, addr) \
    asm volatile("ldmatrix.sync.aligned.m8n8.x2.shared.b16 {%0,%1}, [%2];" \
                 : "=r"(r0), "=r"(r1) : "r"(addr))
__device__ __forceinline__ void mma_bf16(float* d, uint32_t a0, uint32_t a1,
                                         uint32_t a2, uint32_t a3,
                                         uint32_t b0, uint32_t b1) {
    asm volatile(
        "mma.sync.aligned.m16n8k16.row.col.f32.bf16.bf16.f32 "
        "{%0,%1,%2,%3},{%4,%5,%6,%7},{%8,%9},{%0,%1,%2,%3};"
        : "+f"(d[0]), "+f"(d[1]), "+f"(d[2]), "+f"(d[3])
        : "r"(a0), "r"(a1), "r"(a2), "r"(a3), "r"(b0), "r"(b1));
}

__global__ __launch_bounds__(256) void gemm_bf16_dual(
    const __nv_bfloat16* __restrict__ Ahi, const __nv_bfloat16* __restrict__ Alo,
    const __nv_bfloat16* __restrict__ BhiL, const __nv_bfloat16* __restrict__ BloL,
    const __nv_bfloat16* __restrict__ BhiR, const __nv_bfloat16* __restrict__ BloR,
    const float* __restrict__ biasL, const float* __restrict__ biasR,
    float* __restrict__ CL, float* __restrict__ CR, int M, int K, int Ncols) {
    const int SA = 40;
    __shared__ __align__(16) uint16_t As_h[128 * 40];
    __shared__ __align__(16) uint16_t As_l[128 * 40];
    __shared__ __align__(16) uint16_t Bs_h[64 * 40];
    __shared__ __align__(16) uint16_t Bs_l[64 * 40];

    const __nv_bfloat16* BhiT = blockIdx.z ? BhiR : BhiL;
    const __nv_bfloat16* BloT = blockIdx.z ? BloR : BloL;
    const float* bias = blockIdx.z ? biasR : biasL;
    float* C = blockIdx.z ? CR : CL;

    int tid = threadIdx.x, lane = tid & 31, warp = tid >> 5;
    int warpM = warp & 3, warpN = warp >> 2;
    int row0 = blockIdx.y * 128, col0 = blockIdx.x * 64;

    float acc[2][4][4];
    #pragma unroll
    for (int mt = 0; mt < 2; mt++)
        #pragma unroll
        for (int nt = 0; nt < 4; nt++)
            #pragma unroll
            for (int i = 0; i < 4; i++) acc[mt][nt][i] = 0.f;

    uint32_t aadH[2], aadL[2], badH[4], badL[4];
    {
        int ar = (lane & 7) + ((lane >> 3) & 1) * 8;
        int ac = (lane >> 4) * 8;
        #pragma unroll
        for (int mt = 0; mt < 2; mt++) {
            int r = warpM * 32 + mt * 16 + ar;
            aadH[mt] = smem_u32(As_h) + (uint32_t)(r * SA + ac) * 2;
            aadL[mt] = smem_u32(As_l) + (uint32_t)(r * SA + ac) * 2;
        }
        int l16 = lane & 15;
        int bn = l16 & 7;
        int bc = ((l16 >> 3) & 1) * 8;
        #pragma unroll
        for (int nt = 0; nt < 4; nt++) {
            int n = warpN * 32 + nt * 8 + bn;
            badH[nt] = smem_u32(Bs_h) + (uint32_t)(n * SA + bc) * 2;
            badL[nt] = smem_u32(Bs_l) + (uint32_t)(n * SA + bc) * 2;
        }
    }

    for (int k0 = 0; k0 < K; k0 += 32) {
        #pragma unroll
        for (int it = 0; it < 2; it++) {
            int idx = tid + it * 256;
            int r = idx >> 2, sk = (idx & 3) * 8;
            int grow = row0 + r;
            uint4 vh = make_uint4(0, 0, 0, 0), vl = make_uint4(0, 0, 0, 0);
            if (grow < M) {
                size_t off = (size_t)grow * K + k0 + sk;
                vh = *(const uint4*)(Ahi + off);
                vl = *(const uint4*)(Alo + off);
            }
            *(uint4*)&As_h[r * SA + sk] = vh;
            *(uint4*)&As_l[r * SA + sk] = vl;
        }
        {
            int r = tid >> 2, sk = (tid & 3) * 8;
            size_t off = (size_t)(col0 + r) * K + k0 + sk;
            *(uint4*)&Bs_h[r * SA + sk] = *(const uint4*)(BhiT + off);
            *(uint4*)&Bs_l[r * SA + sk] = *(const uint4*)(BloT + off);
        }
        __syncthreads();

        #pragma unroll
        for (int ks = 0; ks < 32; ks += 16) {
            uint32_t kb = ks * 2;
            uint32_t ah[2][4], al[2][4], bh[4][2], bl[4][2];
            #pragma unroll
            for (int mt = 0; mt < 2; mt++) {
                LDSM_X4(ah[mt][0], ah[mt][1], ah[mt][2], ah[mt][3], aadH[mt] + kb);
                LDSM_X4(al[mt][0], al[mt][1], al[mt][2], al[mt][3], aadL[mt] + kb);
            }
            #pragma unroll
            for (int nt = 0; nt < 4; nt++) {
                LDSM_X2(bh[nt][0], bh[nt][1], badH[nt] + kb);
                LDSM_X2(bl[nt][0], bl[nt][1], badL[nt] + kb);
            }
            #pragma unroll
            for (int mt = 0; mt < 2; mt++)
                #pragma unroll
                for (int nt = 0; nt < 4; nt++) {
                    mma_bf16(acc[mt][nt], ah[mt][0], ah[mt][1], ah[mt][2], ah[mt][3],
                             bl[nt][0], bl[nt][1]);
                    mma_bf16(acc[mt][nt], al[mt][0], al[mt][1], al[mt][2], al[mt][3],
                             bh[nt][0], bh[nt][1]);
                    mma_bf16(acc[mt][nt], ah[mt][0], ah[mt][1], ah[mt][2], ah[mt][3],
                             bh[nt][0], bh[nt][1]);
                }
        }
        __syncthreads();
    }

    int g = lane >> 2, tg = lane & 3;
    #pragma unroll
    for (int nt = 0; nt < 4; nt++) {
        int col = col0 + warpN * 32 + nt * 8 + 2 * tg;
        float2 bv = *(const float2*)(bias + col);
        #pragma unroll
        for (int mt = 0; mt < 2; mt++) {
            int r = row0 + warpM * 32 + mt * 16 + g;
            if (r < M) {
                float2 v = make_float2(acc[mt][nt][0] + bv.x, acc[mt][nt][1] + bv.y);
                *(float2*)(C + (size_t)r * Ncols + col) = v;
            }
            if (r + 8 < M) {
                float2 v = make_float2(acc[mt][nt][2] + bv.x, acc[mt][nt][3] + bv.y);
                *(float2*)(C + (size_t)(r + 8) * Ncols + col) = v;
            }
        }
    }
}

// ---------------- fused edge aggregation, H=4: ONE warp per node (R13 structure) ---
// Channel math in packed f32x2 (4 pairs per lane): z per pair = add2 + 4x fma2;
// accumulation per pair = fma2. Value+index pipelined 2-edge stages.
__global__ void edge_agg_h4(const int* __restrict__ rowptr, const int* __restrict__ csr_src,
                            const float4* __restrict__ csr_ea,
                            const float* __restrict__ xl, const float* __restrict__ xr,
                            const float* __restrict__ We, const float* __restrict__ att,
                            const float* __restrict__ bias,
                            __nv_bfloat16* __restrict__ out_hi,
                            __nv_bfloat16* __restrict__ out_lo) {
    int w = (blockIdx.x * blockDim.x + threadIdx.x) >> 5;  // node
    int lane = threadIdx.x & 31;
    if (w >= N_NODES) return;
    int n = w;
    int c = lane * 8;

    ull xrp[4], wevp[4][4];
    float atv[8];
    {
        float4 v0 = *(const float4*)(xr + (size_t)n * 256 + c);
        float4 v1 = *(const float4*)(xr + (size_t)n * 256 + c + 4);
        xrp[0] = pk2(v0.x, v0.y); xrp[1] = pk2(v0.z, v0.w);
        xrp[2] = pk2(v1.x, v1.y); xrp[3] = pk2(v1.z, v1.w);
        v0 = *(const float4*)(att + c);
        v1 = *(const float4*)(att + c + 4);
        atv[0] = v0.x; atv[1] = v0.y; atv[2] = v0.z; atv[3] = v0.w;
        atv[4] = v1.x; atv[5] = v1.y; atv[6] = v1.z; atv[7] = v1.w;
        #pragma unroll
        for (int f = 0; f < 4; f++) {
            v0 = *(const float4*)(We + f * 256 + c);
            v1 = *(const float4*)(We + f * 256 + c + 4);
            wevp[f][0] = pk2(v0.x, v0.y); wevp[f][1] = pk2(v0.z, v0.w);
            wevp[f][2] = pk2(v1.x, v1.y); wevp[f][3] = pk2(v1.z, v1.w);
        }
    }

    float s = 0.f;
    ull ap[4] = {0ull, 0ull, 0ull, 0ull};
    int beg = rowptr[n], end = rowptr[n + 1];

    float4 ce0 = make_float4(0, 0, 0, 0), ce1 = ce0;
    float4 xa0 = ce0, xb0 = ce0, xa1 = ce0, xb1 = ce0;
    if (beg + 1 < end) {
        int s0i = csr_src[beg], s1i = csr_src[beg + 1];
        ce0 = csr_ea[beg];
        ce1 = csr_ea[beg + 1];
        xa0 = *(const float4*)(xl + (size_t)s0i * 256 + c);
        xb0 = *(const float4*)(xl + (size_t)s0i * 256 + c + 4);
        xa1 = *(const float4*)(xl + (size_t)s1i * 256 + c);
        xb1 = *(const float4*)(xl + (size_t)s1i * 256 + c + 4);
    }

    int i = beg;
    for (; i + 1 < end; i += 2) {
        float4 ne0 = ce0, ne1 = ce1, nxa0 = xa0, nxb0 = xb0, nxa1 = xa1, nxb1 = xb1;
        if (i + 3 < end) {
            int s0i = csr_src[i + 2], s1i = csr_src[i + 3];
            ne0 = csr_ea[i + 2];
            ne1 = csr_ea[i + 3];
            nxa0 = *(const float4*)(xl + (size_t)s0i * 256 + c);
            nxb0 = *(const float4*)(xl + (size_t)s0i * 256 + c + 4);
            nxa1 = *(const float4*)(xl + (size_t)s1i * 256 + c);
            nxb1 = *(const float4*)(xl + (size_t)s1i * 256 + c + 4);
        }

        ull xp0[4] = {pk2(xa0.x, xa0.y), pk2(xa0.z, xa0.w), pk2(xb0.x, xb0.y), pk2(xb0.z, xb0.w)};
        ull xp1[4] = {pk2(xa1.x, xa1.y), pk2(xa1.z, xa1.w), pk2(xb1.x, xb1.y), pk2(xb1.z, xb1.w)};
        ull e0x = pk2(ce0.x, ce0.x), e0y = pk2(ce0.y, ce0.y);
        ull e0z = pk2(ce0.z, ce0.z), e0w = pk2(ce0.w, ce0.w);
        ull e1x = pk2(ce1.x, ce1.x), e1y = pk2(ce1.y, ce1.y);
        ull e1z = pk2(ce1.z, ce1.z), e1w = pk2(ce1.w, ce1.w);

        float t0 = 0.f, t1 = 0.f;
        #pragma unroll
        for (int k = 0; k < 4; k++) {
            ull zp0 = add2(xp0[k], xrp[k]);
            zp0 = fma2(e0x, wevp[0][k], zp0);
            zp0 = fma2(e0y, wevp[1][k], zp0);
            zp0 = fma2(e0z, wevp[2][k], zp0);
            zp0 = fma2(e0w, wevp[3][k], zp0);
            ull zp1 = add2(xp1[k], xrp[k]);
            zp1 = fma2(e1x, wevp[0][k], zp1);
            zp1 = fma2(e1y, wevp[1][k], zp1);
            zp1 = fma2(e1z, wevp[2][k], zp1);
            zp1 = fma2(e1w, wevp[3][k], zp1);
            float za, zb;
            upk2(za, zb, zp0);
            za = za > 0.f ? za : 0.2f * za;
            zb = zb > 0.f ? zb : 0.2f * zb;
            t0 += za * atv[2 * k] + zb * atv[2 * k + 1];
            upk2(za, zb, zp1);
            za = za > 0.f ? za : 0.2f * za;
            zb = zb > 0.f ? zb : 0.2f * zb;
            t1 += za * atv[2 * k] + zb * atv[2 * k + 1];
        }
        #pragma unroll
        for (int o = 4; o > 0; o >>= 1) {
            t0 += __shfl_xor_sync(0xFFFFFFFFu, t0, o);
            t1 += __shfl_xor_sync(0xFFFFFFFFu, t1, o);
        }
        float p0 = __expf(t0), p1 = __expf(t1);
        s += p0 + p1;
        ull pp0 = pk2(p0, p0), pp1 = pk2(p1, p1);
        #pragma unroll
        for (int k = 0; k < 4; k++) {
            ap[k] = fma2(pp0, xp0[k], ap[k]);
            ap[k] = fma2(pp1, xp1[k], ap[k]);
        }

        ce0 = ne0; ce1 = ne1;
        xa0 = nxa0; xb0 = nxb0; xa1 = nxa1; xb1 = nxb1;
    }
    if (i < end) {
        int sn = csr_src[i];
        float4 eav = csr_ea[i];
        float4 xa = *(const float4*)(xl + (size_t)sn * 256 + c);
        float4 xb = *(const float4*)(xl + (size_t)sn * 256 + c + 4);
        ull xp[4] = {pk2(xa.x, xa.y), pk2(xa.z, xa.w), pk2(xb.x, xb.y), pk2(xb.z, xb.w)};
        ull ex = pk2(eav.x, eav.x), ey = pk2(eav.y, eav.y);
        ull ez = pk2(eav.z, eav.z), ew = pk2(eav.w, eav.w);
        float t = 0.f;
        #pragma unroll
        for (int k = 0; k < 4; k++) {
            ull zp = add2(xp[k], xrp[k]);
            zp = fma2(ex, wevp[0][k], zp);
            zp = fma2(ey, wevp[1][k], zp);
            zp = fma2(ez, wevp[2][k], zp);
            zp = fma2(ew, wevp[3][k], zp);
            float za, zb;
            upk2(za, zb, zp);
            za = za > 0.f ? za : 0.2f * za;
            zb = zb > 0.f ? zb : 0.2f * zb;
            t += za * atv[2 * k] + zb * atv[2 * k + 1];
        }
        #pragma unroll
        for (int o = 4; o > 0; o >>= 1) t += __shfl_xor_sync(0xFFFFFFFFu, t, o);
        float p = __expf(t);
        s += p;
        ull pp = pk2(p, p);
        #pragma unroll
        for (int k = 0; k < 4; k++) ap[k] = fma2(pp, xp[k], ap[k]);
    }

    float inv = 1.f / (s + 1e-16f);
    float a[8];
    upk2(a[0], a[1], ap[0]);
    upk2(a[2], a[3], ap[1]);
    upk2(a[4], a[5], ap[2]);
    upk2(a[6], a[7], ap[3]);
    float4 bv0 = *(const float4*)(bias + c);
    float4 bv1 = *(const float4*)(bias + c + 4);
    float bb[8] = {bv0.x, bv0.y, bv0.z, bv0.w, bv1.x, bv1.y, bv1.z, bv1.w};
    uint16_t hv[8], lv[8];
    #pragma unroll
    for (int j = 0; j < 8; j++) {
        float r = a[j] * inv + bb[j];
        r = r > 0.f ? r : expm1f(r);   // ELU
        __nv_bfloat16 h = __float2bfloat16(r);
        __nv_bfloat16 l = __float2bfloat16(r - __bfloat162float(h));
        hv[j] = *(uint16_t*)&h;
        lv[j] = *(uint16_t*)&l;
    }
    *(uint4*)(out_hi + (size_t)n * 256 + c) = *(uint4*)hv;
    *(uint4*)(out_lo + (size_t)n * 256 + c) = *(uint4*)lv;
}

// ---------------- edge aggregation, H=1 (layer 3) + fused global-mean-pool --------
__global__ void edge_agg_h1_pool(const int* __restrict__ rowptr, const int* __restrict__ csr_src,
                                 const float4* __restrict__ csr_ea,
                                 const float* __restrict__ xl, const float* __restrict__ xr,
                                 const float* __restrict__ We, const float* __restrict__ att,
                                 const float* __restrict__ bias, const int* __restrict__ batch,
                                 float* __restrict__ sums, int* __restrict__ cnt) {
    const int D = 64;
    int w = (blockIdx.x * blockDim.x + threadIdx.x) >> 5;
    int lane = threadIdx.x & 31;
    int n = w;
    if (n >= N_NODES) return;

    int c = 2 * lane;
    float2 xrv = *(const float2*)(xr + (size_t)n * D + c);
    float2 atv = *(const float2*)(att + c);
    float2 wev[4];
    #pragma unroll
    for (int f = 0; f < 4; f++) wev[f] = *(const float2*)(We + f * D + c);

    float s0 = 0.f, a00 = 0.f, a01 = 0.f;
    float s1 = 0.f, a10 = 0.f, a11 = 0.f;
    int beg = rowptr[n], end = rowptr[n + 1];

    int i = beg;
    for (; i + 3 < end; i += 4) {
        int sn0 = csr_src[i], sn1 = csr_src[i + 1], sn2 = csr_src[i + 2], sn3 = csr_src[i + 3];
        float4 e0 = csr_ea[i], e1 = csr_ea[i + 1], e2 = csr_ea[i + 2], e3 = csr_ea[i + 3];
        float2 x0 = *(const float2*)(xl + (size_t)sn0 * D + c);
        float2 x1 = *(const float2*)(xl + (size_t)sn1 * D + c);
        float2 x2 = *(const float2*)(xl + (size_t)sn2 * D + c);
        float2 x3 = *(const float2*)(xl + (size_t)sn3 * D + c);

        float za, zb, t0, t1, t2, t3;
        za = x0.x + xrv.x + e0.x * wev[0].x + e0.y * wev[1].x + e0.z * wev[2].x + e0.w * wev[3].x;
        zb = x0.y + xrv.y + e0.x * wev[0].y + e0.y * wev[1].y + e0.z * wev[2].y + e0.w * wev[3].y;
        za = za > 0.f ? za : 0.2f * za; zb = zb > 0.f ? zb : 0.2f * zb;
        t0 = za * atv.x + zb * atv.y;
        za = x1.x + xrv.x + e1.x * wev[0].x + e1.y * wev[1].x + e1.z * wev[2].x + e1.w * wev[3].x;
        zb = x1.y + xrv.y + e1.x * wev[0].y + e1.y * wev[1].y + e1.z * wev[2].y + e1.w * wev[3].y;
        za = za > 0.f ? za : 0.2f * za; zb = zb > 0.f ? zb : 0.2f * zb;
        t1 = za * atv.x + zb * atv.y;
        za = x2.x + xrv.x + e2.x * wev[0].x + e2.y * wev[1].x + e2.z * wev[2].x + e2.w * wev[3].x;
        zb = x2.y + xrv.y + e2.x * wev[0].y + e2.y * wev[1].y + e2.z * wev[2].y + e2.w * wev[3].y;
        za = za > 0.f ? za : 0.2f * za; zb = zb > 0.f ? zb : 0.2f * zb;
        t2 = za * atv.x + zb * atv.y;
        za = x3.x + xrv.x + e3.x * wev[0].x + e3.y * wev[1].x + e3.z * wev[2].x + e3.w * wev[3].x;
        zb = x3.y + xrv.y + e3.x * wev[0].y + e3.y * wev[1].y + e3.z * wev[2].y + e3.w * wev[3].y;
        za = za > 0.f ? za : 0.2f * za; zb = zb > 0.f ? zb : 0.2f * zb;
        t3 = za * atv.x + zb * atv.y;

        #pragma unroll
        for (int o = 16; o > 0; o >>= 1) {
            t0 += __shfl_xor_sync(0xFFFFFFFFu, t0, o);
            t1 += __shfl_xor_sync(0xFFFFFFFFu, t1, o);
            t2 += __shfl_xor_sync(0xFFFFFFFFu, t2, o);
            t3 += __shfl_xor_sync(0xFFFFFFFFu, t3, o);
        }
        float p0 = __expf(t0), p1 = __expf(t1), p2 = __expf(t2), p3 = __expf(t3);
        s0 += p0; a00 += p0 * x0.x; a01 += p0 * x0.y;
        s1 += p1; a10 += p1 * x1.x; a11 += p1 * x1.y;
        s0 += p2; a00 += p2 * x2.x; a01 += p2 * x2.y;
        s1 += p3; a10 += p3 * x3.x; a11 += p3 * x3.y;
    }
    for (; i < end; i++) {
        int sn = csr_src[i];
        float4 eav = csr_ea[i];
        float2 xv = *(const float2*)(xl + (size_t)sn * D + c);
        float z0 = xv.x + xrv.x + eav.x * wev[0].x + eav.y * wev[1].x + eav.z * wev[2].x + eav.w * wev[3].x;
        float z1 = xv.y + xrv.y + eav.x * wev[0].y + eav.y * wev[1].y + eav.z * wev[2].y + eav.w * wev[3].y;
        z0 = z0 > 0.f ? z0 : 0.2f * z0;
        z1 = z1 > 0.f ? z1 : 0.2f * z1;
        float t = z0 * atv.x + z1 * atv.y;
        #pragma unroll
        for (int o = 16; o > 0; o >>= 1) t += __shfl_xor_sync(0xFFFFFFFFu, t, o);
        float p = __expf(t);
        s0 += p; a00 += p * xv.x; a01 += p * xv.y;
    }
    float s = s0 + s1;
    float a0 = a00 + a10;
    float a1 = a01 + a11;

    float inv = 1.f / (s + 1e-16f);
    float2 bv = *(const float2*)(bias + c);
    float r0 = a0 * inv + bv.x;
    float r1 = a1 * inv + bv.y;

    int g = batch[n];
    atomicAdd(&sums[g * 64 + c], r0);
    atomicAdd(&sums[g * 64 + c + 1], r1);
    if (lane == 0) atomicAdd(&cnt[g], 1);
}

// ---------------- MLP head ----------------
__global__ void mlp_k(const float* __restrict__ sums, const int* __restrict__ cnt,
                      const float* __restrict__ mW1, const float* __restrict__ mb1,
                      const float* __restrict__ mW2, const float* __restrict__ mb2,
                      const float* __restrict__ mW3, const float* __restrict__ mb3,
                      float* __restrict__ out) {
    __shared__ float gv[64];
    __shared__ float h1[32];
    __shared__ float h2[16];
    int g = blockIdx.x, t = threadIdx.x;
    float cf = fmaxf((float)cnt[g], 1.f);
    gv[t] = sums[g * 64 + t] / cf;
    __syncthreads();
    if (t < 32) {
        float a = mb1[t];
        #pragma unroll
        for (int k = 0; k < 64; k++) a += gv[k] * mW1[k * 32 + t];
        h1[t] = fmaxf(a, 0.f);
    }
    __syncthreads();
    if (t < 16) {
        float a = mb2[t];
        #pragma unroll
        for (int k = 0; k < 32; k++) a += h1[k] * mW2[k * 16 + t];
        h2[t] = fmaxf(a, 0.f);
    }
    __syncthreads();
    if (t < 4) {
        float a = mb3[t];
        #pragma unroll
        for (int k = 0; k < 16; k++) a += h2[k] * mW3[k * 4 + t];
        out[g * 4 + t] = a;
    }
}

// ---------------- launch ----------------
extern "C" void kernel_launch(void* const* d_in, const int* in_sizes, int n_in,
                              void* d_out, int out_size) {
    (void)in_sizes; (void)n_in; (void)out_size;
    const float* x     = (const float*)d_in[0];
    const int*   ei    = (const int*)d_in[1];
    const float* ea    = (const float*)d_in[2];
    const int*   batch = (const int*)d_in[3];
    const float* Wl1 = (const float*)d_in[4],  *bl1 = (const float*)d_in[5];
    const float* Wr1 = (const float*)d_in[6],  *br1 = (const float*)d_in[7];
    const float* We1 = (const float*)d_in[8],  *att1 = (const float*)d_in[9],  *bias1 = (const float*)d_in[10];
    const float* Wl2 = (const float*)d_in[11], *bl2 = (const float*)d_in[12];
    const float* Wr2 = (const float*)d_in[13], *br2 = (const float*)d_in[14];
    const float* We2 = (const float*)d_in[15], *att2 = (const float*)d_in[16], *bias2 = (const float*)d_in[17];
    const float* Wl3 = (const float*)d_in[18], *bl3 = (const float*)d_in[19];
    const float* Wr3 = (const float*)d_in[20], *br3 = (const float*)d_in[21];
    const float* We3 = (const float*)d_in[22], *att3 = (const float*)d_in[23], *bias3 = (const float*)d_in[24];
    const float* mW1 = (const float*)d_in[25], *mb1 = (const float*)d_in[26];
    const float* mW2 = (const float*)d_in[27], *mb2 = (const float*)d_in[28];
    const float* mW3 = (const float*)d_in[29], *mb3 = (const float*)d_in[30];
    float* out = (float*)d_out;

    const int* srcp = ei;
    const int* dstp = ei + N_EDGES;

    float *xl, *xr, *sums;
    int *deg, *rowptr, *cursor, *csr_src, *cnt;
    float4* csr_ea;
    __nv_bfloat16 *ahi, *alo, *whL, *wlL, *whR, *wlR;
    cudaGetSymbolAddress((void**)&xl, g_xl);
    cudaGetSymbolAddress((void**)&xr, g_xr);
    cudaGetSymbolAddress((void**)&sums, g_sums);
    cudaGetSymbolAddress((void**)&deg, g_deg);
    cudaGetSymbolAddress((void**)&rowptr, g_rowptr);
    cudaGetSymbolAddress((void**)&cursor, g_cursor);
    cudaGetSymbolAddress((void**)&csr_src, g_csr_src);
    cudaGetSymbolAddress((void**)&csr_ea, g_csr_ea);
    cudaGetSymbolAddress((void**)&cnt, g_cnt);
    cudaGetSymbolAddress((void**)&ahi, g_ahi);
    cudaGetSymbolAddress((void**)&alo, g_alo);
    cudaGetSymbolAddress((void**)&whL, g_whL);
    cudaGetSymbolAddress((void**)&wlL, g_wlL);
    cudaGetSymbolAddress((void**)&whR, g_whR);
    cudaGetSymbolAddress((void**)&wlR, g_wlR);

    // CSR by destination (shared by all 3 layers)
    zero_i32<<<(N_NODES + 255) / 256, 256>>>(deg, N_NODES);
    hist_k<<<(N_EDGES + 255) / 256, 256>>>(dstp, deg);
    scan_k<<<1, 1024>>>(deg, rowptr, cursor);
    scatter_k<<<(N_EDGES + 255) / 256, 256>>>(srcp, dstp, (const float4*)ea, cursor, csr_src, csr_ea);

    // layer-1 dual GEMM (xl + xr in one pass)
    gemm_k12_dual<<<(N_NODES + 31) / 32, 256>>>(x, Wl1, bl1, Wr1, br1, xl, xr);

    edge_agg_h4<<<2500, 256>>>(rowptr, csr_src, csr_ea, xl, xr, We1, att1, bias1, ahi, alo);

    // ---- layer 2 (256 -> 256, H=4): one dual launch for L+R ----
    splitW_dual<<<(256 * 256 + 255) / 256, 256>>>(Wl2, Wr2, whL, wlL, whR, wlR, 256, 256);
    gemm_bf16_dual<<<dim3(4, 157, 2), 256>>>(ahi, alo, whL, wlL, whR, wlR, bl2, br2,
                                             xl, xr, N_NODES, 256, 256);
    edge_agg_h4<<<2500, 256>>>(rowptr, csr_src, csr_ea, xl, xr, We2, att2, bias2, ahi, alo);

    // ---- layer 3 (256 -> 64, H=1, no ELU), pool fused into epilogue ----
    splitW_dual<<<(256 * 64 + 255) / 256, 256>>>(Wl3, Wr3, whL, wlL, whR, wlR, 256, 64);
    gemm_bf16_dual<<<dim3(1, 157, 2), 256>>>(ahi, alo, whL, wlL, whR, wlR, bl3, br3,
                                             xl, xr, N_NODES, 256, 64);
    zero_f32<<<(N_GRAPHS * 64 + 255) / 256, 256>>>(sums, N_GRAPHS * 64);
    zero_i32<<<(N_GRAPHS + 255) / 256, 256>>>(cnt, N_GRAPHS);
    edge_agg_h1_pool<<<2500, 256>>>(rowptr, csr_src, csr_ea, xl, xr, We3, att3, bias3,
                                    batch, sums, cnt);

    // ---- MLP head ----
    mlp_k<<<N_GRAPHS, 64>>>(sums, cnt, mW1, mb1, mW2, mb2, mW3, mb3, out);
}

// round 17
// speedup vs baseline: 1.0166x; 1.0019x over previous
#include <cuda_runtime.h>
#include <cuda_bf16.h>
#include <math.h>
#include <stdint.h>

#define N_NODES  20000
#define N_EDGES  320000
#define N_GRAPHS 1000

// ---------------- static device scratch (no allocations allowed) ----------------
__device__ float    g_xl[N_NODES * 256];
__device__ float    g_xr[N_NODES * 256];
__device__ uint16_t g_ahi[N_NODES * 256];
__device__ uint16_t g_alo[N_NODES * 256];
__device__ uint16_t g_whL[256 * 256];
__device__ uint16_t g_wlL[256 * 256];
__device__ uint16_t g_whR[256 * 256];
__device__ uint16_t g_wlR[256 * 256];
__device__ int      g_deg[N_NODES];
__device__ int      g_rowptr[N_NODES + 1];
__device__ int      g_cursor[N_NODES];
__device__ int      g_csr_src[N_EDGES];
__device__ float4   g_csr_ea[N_EDGES];
__device__ float    g_sums[N_GRAPHS * 64];
__device__ int      g_cnt[N_GRAPHS];

// ---------------- utility kernels ----------------
__global__ void zero_i32(int* p, int n) {
    int i = blockIdx.x * blockDim.x + threadIdx.x;
    if (i < n) p[i] = 0;
}
__global__ void zero_pool(float* sums, int* cnt) {
    int i = blockIdx.x * blockDim.x + threadIdx.x;
    if (i < N_GRAPHS * 64) sums[i] = 0.f;
    if (i < N_GRAPHS) cnt[i] = 0;
}
__global__ void hist_k(const int* __restrict__ dst, int* __restrict__ deg) {
    int e = blockIdx.x * blockDim.x + threadIdx.x;
    if (e < N_EDGES) atomicAdd(&deg[dst[e]], 1);
}

__global__ void scan_k(const int* __restrict__ deg, int* __restrict__ rowptr,
                       int* __restrict__ cursor) {
    __shared__ int sh[1024];
    const int CH = 20;
    int t = threadIdx.x;
    int base = t * CH;
    int loc[CH];
    int s = 0;
    #pragma unroll
    for (int i = 0; i < CH; i++) {
        int idx = base + i;
        int v = (idx < N_NODES) ? deg[idx] : 0;
        loc[i] = s;
        s += v;
    }
    sh[t] = s;
    __syncthreads();
    for (int off = 1; off < 1024; off <<= 1) {
        int v = (t >= off) ? sh[t - off] : 0;
        __syncthreads();
        sh[t] += v;
        __syncthreads();
    }
    int pre = (t > 0) ? sh[t - 1] : 0;
    #pragma unroll
    for (int i = 0; i < CH; i++) {
        int idx = base + i;
        if (idx < N_NODES) {
            int v = pre + loc[i];
            rowptr[idx] = v;
            cursor[idx] = v;
        }
    }
    if (t == 1023) rowptr[N_NODES] = sh[1023];
}

__global__ void scatter_k(const int* __restrict__ src, const int* __restrict__ dst,
                          const float4* __restrict__ ea, int* __restrict__ cursor,
                          int* __restrict__ csr_src, float4* __restrict__ csr_ea) {
    int e = blockIdx.x * blockDim.x + threadIdx.x;
    if (e < N_EDGES) {
        int p = atomicAdd(&cursor[dst[e]], 1);
        csr_src[p] = src[e];
        csr_ea[p] = ea[e];
    }
}

// dual W split: both L and R weights, W[K][Nc] fp32 -> transposed [Nc][K] bf16 hi/lo
__global__ void splitW_dual(const float* __restrict__ WL, const float* __restrict__ WR,
                            __nv_bfloat16* __restrict__ hiL, __nv_bfloat16* __restrict__ loL,
                            __nv_bfloat16* __restrict__ hiR, __nv_bfloat16* __restrict__ loR,
                            int K, int Nc) {
    int i = blockIdx.x * blockDim.x + threadIdx.x;
    if (i < K * Nc) {
        int k = i / Nc, n = i - k * Nc;
        float v = WL[i];
        __nv_bfloat16 h = __float2bfloat16(v);
        hiL[(size_t)n * K + k] = h;
        loL[(size_t)n * K + k] = __float2bfloat16(v - __bfloat162float(h));
        v = WR[i];
        h = __float2bfloat16(v);
        hiR[(size_t)n * K + k] = h;
        loR[(size_t)n * K + k] = __float2bfloat16(v - __bfloat162float(h));
    }
}

// ---------------- layer-1 dual GEMM (K=12 -> 256 for both Wl and Wr) ----------------
__global__ void gemm_k12_dual(const float* __restrict__ x,
                              const float* __restrict__ WL, const float* __restrict__ bL,
                              const float* __restrict__ WR, const float* __restrict__ bR,
                              float* __restrict__ xl, float* __restrict__ xr) {
    __shared__ float WsL[12 * 256];
    __shared__ float WsR[12 * 256];
    __shared__ float xs[32 * 12];
    int tid = threadIdx.x;
    int r0 = blockIdx.x * 32;
    for (int i = tid; i < 12 * 256; i += 256) {
        WsL[i] = WL[i];
        WsR[i] = WR[i];
    }
    for (int i = tid; i < 32 * 12; i += 256) {
        int r = r0 + i / 12;
        xs[i] = (r < N_NODES) ? x[(size_t)r * 12 + (i % 12)] : 0.f;
    }
    __syncthreads();
    float bbL = bL[tid], bbR = bR[tid];
    for (int r = 0; r < 32; r++) {
        int gr = r0 + r;
        if (gr >= N_NODES) break;
        float accL = bbL, accR = bbR;
        #pragma unroll
        for (int k = 0; k < 12; k++) {
            float xv = xs[r * 12 + k];
            accL += xv * WsL[k * 256 + tid];
            accR += xv * WsR[k * 256 + tid];
        }
        xl[(size_t)gr * 256 + tid] = accL;
        xr[(size_t)gr * 256 + tid] = accR;
    }
}

// ---------------- bf16 mma.sync GEMM, cp.async double-buffered ----------------
__device__ __forceinline__ uint32_t smem_u32(const void* p) {
    uint32_t a;
    asm("{ .reg .u64 t; cvta.to.shared.u64 t, %1; cvt.u32.u64 %0, t; }" : "=r"(a) : "l"(p));
    return a;
}
#define LDSM_X4(r0, r1, r2, r3, addr) \
    asm volatile("ldmatrix.sync.aligned.m8n8.x4.shared.b16 {%0,%1,%2,%3}, [%4];" \
                 : "=r"(r0), "=r"(r1), "=r"(r2), "=r"(r3) : "r"(addr))
#define LDSM_X2(r0, r1, addr) \
    asm volatile("ldmatrix.sync.aligned.m8n8.x2.shared.b16 {%0,%1}, [%2];" \
                 : "=r"(r0), "=r"(r1) : "r"(addr))
__device__ __forceinline__ void mma_bf16(float* d, uint32_t a0, uint32_t a1,
                                         uint32_t a2, uint32_t a3,
                                         uint32_t b0, uint32_t b1) {
    asm volatile(
        "mma.sync.aligned.m16n8k16.row.col.f32.bf16.bf16.f32 "
        "{%0,%1,%2,%3},{%4,%5,%6,%7},{%8,%9},{%0,%1,%2,%3};"
        : "+f"(d[0]), "+f"(d[1]), "+f"(d[2]), "+f"(d[3])
        : "r"(a0), "r"(a1), "r"(a2), "r"(a3), "r"(b0), "r"(b1));
}
__device__ __forceinline__ void cp16z(uint32_t dst, const void* src, uint32_t zf) {
    asm volatile("cp.async.cg.shared.global [%0], [%1], 16, %2;"
                 :: "r"(dst), "l"(src), "r"(zf) : "memory");
}

// smem stage layout (bytes): AH 0, AL 10240, BH 20480, BL 25600; stage size 30720
#define GOFF_AH 0u
#define GOFF_AL 10240u
#define GOFF_BH 20480u
#define GOFF_BL 25600u
#define GSTAGE  30720u

__global__ __launch_bounds__(256) void gemm_bf16_dual(
    const __nv_bfloat16* __restrict__ Ahi, const __nv_bfloat16* __restrict__ Alo,
    const __nv_bfloat16* __restrict__ BhiL, const __nv_bfloat16* __restrict__ BloL,
    const __nv_bfloat16* __restrict__ BhiR, const __nv_bfloat16* __restrict__ BloR,
    const float* __restrict__ biasL, const float* __restrict__ biasR,
    float* __restrict__ CL, float* __restrict__ CR, int M, int K, int Ncols) {
    extern __shared__ __align__(16) uint16_t smem_dyn[];
    const int SA = 40;

    const __nv_bfloat16* BhiT = blockIdx.z ? BhiR : BhiL;
    const __nv_bfloat16* BloT = blockIdx.z ? BloR : BloL;
    const float* bias = blockIdx.z ? biasR : biasL;
    float* C = blockIdx.z ? CR : CL;

    int tid = threadIdx.x, lane = tid & 31, warp = tid >> 5;
    int warpM = warp & 3, warpN = warp >> 2;
    int row0 = blockIdx.y * 128, col0 = blockIdx.x * 64;
    uint32_t sb = smem_u32(smem_dyn);

    float acc[2][4][4];
    #pragma unroll
    for (int mt = 0; mt < 2; mt++)
        #pragma unroll
        for (int nt = 0; nt < 4; nt++)
            #pragma unroll
            for (int i = 0; i < 4; i++) acc[mt][nt][i] = 0.f;

    // fragment offsets within a stage (bytes)
    uint32_t relAH[2], relAL[2], relBH[4], relBL[4];
    {
        int ar = (lane & 7) + ((lane >> 3) & 1) * 8;
        int ac = (lane >> 4) * 8;
        #pragma unroll
        for (int mt = 0; mt < 2; mt++) {
            int r = warpM * 32 + mt * 16 + ar;
            relAH[mt] = GOFF_AH + (uint32_t)(r * SA + ac) * 2;
            relAL[mt] = GOFF_AL + (uint32_t)(r * SA + ac) * 2;
        }
        int l16 = lane & 15;
        int bn = l16 & 7;
        int bc = ((l16 >> 3) & 1) * 8;
        #pragma unroll
        for (int nt = 0; nt < 4; nt++) {
            int n = warpN * 32 + nt * 8 + bn;
            relBH[nt] = GOFF_BH + (uint32_t)(n * SA + bc) * 2;
            relBL[nt] = GOFF_BL + (uint32_t)(n * SA + bc) * 2;
        }
    }

    // staging geometry: A rows a_r0 / a_r0+64, B row b_r (= tid>>2), seg (tid&3)*8
    int a_r0 = tid >> 2, sk = (tid & 3) * 8;
    int a_r1 = a_r0 + 64;
    int grow0 = row0 + a_r0, grow1 = row0 + a_r1;
    uint32_t zf0 = (grow0 < M) ? 16u : 0u;
    uint32_t zf1 = (grow1 < M) ? 16u : 0u;
    int cg0 = (grow0 < M) ? grow0 : (M - 1);
    int cg1 = (grow1 < M) ? grow1 : (M - 1);
    uint32_t dA0 = (uint32_t)(a_r0 * SA + sk) * 2;
    uint32_t dA1 = (uint32_t)(a_r1 * SA + sk) * 2;
    uint32_t dB = (uint32_t)(a_r0 * SA + sk) * 2;
    size_t srcA0 = (size_t)cg0 * K + sk;
    size_t srcA1 = (size_t)cg1 * K + sk;
    size_t srcB = (size_t)(col0 + a_r0) * K + sk;

    // prologue: stage chunk 0 into buffer 0
    {
        uint32_t base = sb;
        cp16z(base + GOFF_AH + dA0, Ahi + srcA0, zf0);
        cp16z(base + GOFF_AL + dA0, Alo + srcA0, zf0);
        cp16z(base + GOFF_AH + dA1, Ahi + srcA1, zf1);
        cp16z(base + GOFF_AL + dA1, Alo + srcA1, zf1);
        cp16z(base + GOFF_BH + dB, BhiT + srcB, 16u);
        cp16z(base + GOFF_BL + dB, BloT + srcB, 16u);
        asm volatile("cp.async.commit_group;" ::: "memory");
    }

    int nch = K >> 5;
    for (int it = 0; it < nch; it++) {
        uint32_t stBase = sb + (uint32_t)(it & 1) * GSTAGE;
        if (it + 1 < nch) {
            uint32_t nb = sb + (uint32_t)((it + 1) & 1) * GSTAGE;
            int kn = (it + 1) * 32;
            cp16z(nb + GOFF_AH + dA0, Ahi + srcA0 + kn, zf0);
            cp16z(nb + GOFF_AL + dA0, Alo + srcA0 + kn, zf0);
            cp16z(nb + GOFF_AH + dA1, Ahi + srcA1 + kn, zf1);
            cp16z(nb + GOFF_AL + dA1, Alo + srcA1 + kn, zf1);
            cp16z(nb + GOFF_BH + dB, BhiT + srcB + kn, 16u);
            cp16z(nb + GOFF_BL + dB, BloT + srcB + kn, 16u);
            asm volatile("cp.async.commit_group;" ::: "memory");
            asm volatile("cp.async.wait_group 1;" ::: "memory");
        } else {
            asm volatile("cp.async.wait_group 0;" ::: "memory");
        }
        __syncthreads();

        #pragma unroll
        for (int ks = 0; ks < 32; ks += 16) {
            uint32_t kb = ks * 2;
            uint32_t ah[2][4], al[2][4], bh[4][2], bl[4][2];
            #pragma unroll
            for (int mt = 0; mt < 2; mt++) {
                LDSM_X4(ah[mt][0], ah[mt][1], ah[mt][2], ah[mt][3], stBase + relAH[mt] + kb);
                LDSM_X4(al[mt][0], al[mt][1], al[mt][2], al[mt][3], stBase + relAL[mt] + kb);
            }
            #pragma unroll
            for (int nt = 0; nt < 4; nt++) {
                LDSM_X2(bh[nt][0], bh[nt][1], stBase + relBH[nt] + kb);
                LDSM_X2(bl[nt][0], bl[nt][1], stBase + relBL[nt] + kb);
            }
            #pragma unroll
            for (int mt = 0; mt < 2; mt++)
                #pragma unroll
                for (int nt = 0; nt < 4; nt++) {
                    mma_bf16(acc[mt][nt], ah[mt][0], ah[mt][1], ah[mt][2], ah[mt][3],
                             bl[nt][0], bl[nt][1]);
                    mma_bf16(acc[mt][nt], al[mt][0], al[mt][1], al[mt][2], al[mt][3],
                             bh[nt][0], bh[nt][1]);
                    mma_bf16(acc[mt][nt], ah[mt][0], ah[mt][1], ah[mt][2], ah[mt][3],
                             bh[nt][0], bh[nt][1]);
                }
        }
        __syncthreads();
    }

    int g = lane >> 2, tg = lane & 3;
    #pragma unroll
    for (int nt = 0; nt < 4; nt++) {
        int col = col0 + warpN * 32 + nt * 8 + 2 * tg;
        float2 bv = *(const float2*)(bias + col);
        #pragma unroll
        for (int mt = 0; mt < 2; mt++) {
            int r = row0 + warpM * 32 + mt * 16 + g;
            if (r < M) {
                float2 v = make_float2(acc[mt][nt][0] + bv.x, acc[mt][nt][1] + bv.y);
                *(float2*)(C + (size_t)r * Ncols + col) = v;
            }
            if (r + 8 < M) {
                float2 v = make_float2(acc[mt][nt][2] + bv.x, acc[mt][nt][3] + bv.y);
                *(float2*)(C + (size_t)(r + 8) * Ncols + col) = v;
            }
        }
    }
}

// ---------------- fused edge aggregation, H=4: ONE warp per node (R13 exact) -------
__global__ void edge_agg_h4(const int* __restrict__ rowptr, const int* __restrict__ csr_src,
                            const float4* __restrict__ csr_ea,
                            const float* __restrict__ xl, const float* __restrict__ xr,
                            const float* __restrict__ We, const float* __restrict__ att,
                            const float* __restrict__ bias,
                            __nv_bfloat16* __restrict__ out_hi,
                            __nv_bfloat16* __restrict__ out_lo) {
    int w = (blockIdx.x * blockDim.x + threadIdx.x) >> 5;  // node
    int lane = threadIdx.x & 31;
    if (w >= N_NODES) return;
    int n = w;
    int c = lane * 8;

    float xrv[8], atv[8], wev[4][8];
    {
        float4 v0 = *(const float4*)(xr + (size_t)n * 256 + c);
        float4 v1 = *(const float4*)(xr + (size_t)n * 256 + c + 4);
        xrv[0] = v0.x; xrv[1] = v0.y; xrv[2] = v0.z; xrv[3] = v0.w;
        xrv[4] = v1.x; xrv[5] = v1.y; xrv[6] = v1.z; xrv[7] = v1.w;
        v0 = *(const float4*)(att + c);
        v1 = *(const float4*)(att + c + 4);
        atv[0] = v0.x; atv[1] = v0.y; atv[2] = v0.z; atv[3] = v0.w;
        atv[4] = v1.x; atv[5] = v1.y; atv[6] = v1.z; atv[7] = v1.w;
        #pragma unroll
        for (int f = 0; f < 4; f++) {
            v0 = *(const float4*)(We + f * 256 + c);
            v1 = *(const float4*)(We + f * 256 + c + 4);
            wev[f][0] = v0.x; wev[f][1] = v0.y; wev[f][2] = v0.z; wev[f][3] = v0.w;
            wev[f][4] = v1.x; wev[f][5] = v1.y; wev[f][6] = v1.z; wev[f][7] = v1.w;
        }
    }

    float s = 0.f, a[8];
    #pragma unroll
    for (int j = 0; j < 8; j++) a[j] = 0.f;
    int beg = rowptr[n], end = rowptr[n + 1];

    float4 ce0 = make_float4(0, 0, 0, 0), ce1 = ce0;
    float4 xa0 = ce0, xb0 = ce0, xa1 = ce0, xb1 = ce0;
    if (beg + 1 < end) {
        int s0i = csr_src[beg], s1i = csr_src[beg + 1];
        ce0 = csr_ea[beg];
        ce1 = csr_ea[beg + 1];
        xa0 = *(const float4*)(xl + (size_t)s0i * 256 + c);
        xb0 = *(const float4*)(xl + (size_t)s0i * 256 + c + 4);
        xa1 = *(const float4*)(xl + (size_t)s1i * 256 + c);
        xb1 = *(const float4*)(xl + (size_t)s1i * 256 + c + 4);
    }

    int i = beg;
    for (; i + 1 < end; i += 2) {
        float4 ne0 = ce0, ne1 = ce1, nxa0 = xa0, nxb0 = xb0, nxa1 = xa1, nxb1 = xb1;
        if (i + 3 < end) {
            int s0i = csr_src[i + 2], s1i = csr_src[i + 3];
            ne0 = csr_ea[i + 2];
            ne1 = csr_ea[i + 3];
            nxa0 = *(const float4*)(xl + (size_t)s0i * 256 + c);
            nxb0 = *(const float4*)(xl + (size_t)s0i * 256 + c + 4);
            nxa1 = *(const float4*)(xl + (size_t)s1i * 256 + c);
            nxb1 = *(const float4*)(xl + (size_t)s1i * 256 + c + 4);
        }

        float x0[8] = {xa0.x, xa0.y, xa0.z, xa0.w, xb0.x, xb0.y, xb0.z, xb0.w};
        float x1[8] = {xa1.x, xa1.y, xa1.z, xa1.w, xb1.x, xb1.y, xb1.z, xb1.w};
        float t0 = 0.f, t1 = 0.f;
        #pragma unroll
        for (int j = 0; j < 8; j++) {
            float z0 = x0[j] + xrv[j] + ce0.x * wev[0][j] + ce0.y * wev[1][j]
                       + ce0.z * wev[2][j] + ce0.w * wev[3][j];
            float z1 = x1[j] + xrv[j] + ce1.x * wev[0][j] + ce1.y * wev[1][j]
                       + ce1.z * wev[2][j] + ce1.w * wev[3][j];
            z0 = z0 > 0.f ? z0 : 0.2f * z0;
            z1 = z1 > 0.f ? z1 : 0.2f * z1;
            t0 += z0 * atv[j];
            t1 += z1 * atv[j];
        }
        #pragma unroll
        for (int o = 4; o > 0; o >>= 1) {
            t0 += __shfl_xor_sync(0xFFFFFFFFu, t0, o);
            t1 += __shfl_xor_sync(0xFFFFFFFFu, t1, o);
        }
        float p0 = __expf(t0), p1 = __expf(t1);
        s += p0 + p1;
        #pragma unroll
        for (int j = 0; j < 8; j++) a[j] += p0 * x0[j] + p1 * x1[j];

        ce0 = ne0; ce1 = ne1;
        xa0 = nxa0; xb0 = nxb0; xa1 = nxa1; xb1 = nxb1;
    }
    if (i < end) {
        int sn = csr_src[i];
        float4 eav = csr_ea[i];
        float4 xa = *(const float4*)(xl + (size_t)sn * 256 + c);
        float4 xb = *(const float4*)(xl + (size_t)sn * 256 + c + 4);
        float xv[8] = {xa.x, xa.y, xa.z, xa.w, xb.x, xb.y, xb.z, xb.w};
        float t = 0.f;
        #pragma unroll
        for (int j = 0; j < 8; j++) {
            float z = xv[j] + xrv[j] + eav.x * wev[0][j] + eav.y * wev[1][j]
                      + eav.z * wev[2][j] + eav.w * wev[3][j];
            z = z > 0.f ? z : 0.2f * z;
            t += z * atv[j];
        }
        #pragma unroll
        for (int o = 4; o > 0; o >>= 1) t += __shfl_xor_sync(0xFFFFFFFFu, t, o);
        float p = __expf(t);
        s += p;
        #pragma unroll
        for (int j = 0; j < 8; j++) a[j] += p * xv[j];
    }

    float inv = 1.f / (s + 1e-16f);
    float4 bv0 = *(const float4*)(bias + c);
    float4 bv1 = *(const float4*)(bias + c + 4);
    float bb[8] = {bv0.x, bv0.y, bv0.z, bv0.w, bv1.x, bv1.y, bv1.z, bv1.w};
    uint16_t hv[8], lv[8];
    #pragma unroll
    for (int j = 0; j < 8; j++) {
        float r = a[j] * inv + bb[j];
        r = r > 0.f ? r : expm1f(r);   // ELU
        __nv_bfloat16 h = __float2bfloat16(r);
        __nv_bfloat16 l = __float2bfloat16(r - __bfloat162float(h));
        hv[j] = *(uint16_t*)&h;
        lv[j] = *(uint16_t*)&l;
    }
    *(uint4*)(out_hi + (size_t)n * 256 + c) = *(uint4*)hv;
    *(uint4*)(out_lo + (size_t)n * 256 + c) = *(uint4*)lv;
}

// ---------------- edge aggregation, H=1 (layer 3) + fused global-mean-pool --------
__global__ void edge_agg_h1_pool(const int* __restrict__ rowptr, const int* __restrict__ csr_src,
                                 const float4* __restrict__ csr_ea,
                                 const float* __restrict__ xl, const float* __restrict__ xr,
                                 const float* __restrict__ We, const float* __restrict__ att,
                                 const float* __restrict__ bias, const int* __restrict__ batch,
                                 float* __restrict__ sums, int* __restrict__ cnt) {
    const int D = 64;
    int w = (blockIdx.x * blockDim.x + threadIdx.x) >> 5;
    int lane = threadIdx.x & 31;
    int n = w;
    if (n >= N_NODES) return;

    int c = 2 * lane;
    float2 xrv = *(const float2*)(xr + (size_t)n * D + c);
    float2 atv = *(const float2*)(att + c);
    float2 wev[4];
    #pragma unroll
    for (int f = 0; f < 4; f++) wev[f] = *(const float2*)(We + f * D + c);

    float s0 = 0.f, a00 = 0.f, a01 = 0.f;
    float s1 = 0.f, a10 = 0.f, a11 = 0.f;
    int beg = rowptr[n], end = rowptr[n + 1];

    int i = beg;
    for (; i + 3 < end; i += 4) {
        int sn0 = csr_src[i], sn1 = csr_src[i + 1], sn2 = csr_src[i + 2], sn3 = csr_src[i + 3];
        float4 e0 = csr_ea[i], e1 = csr_ea[i + 1], e2 = csr_ea[i + 2], e3 = csr_ea[i + 3];
        float2 x0 = *(const float2*)(xl + (size_t)sn0 * D + c);
        float2 x1 = *(const float2*)(xl + (size_t)sn1 * D + c);
        float2 x2 = *(const float2*)(xl + (size_t)sn2 * D + c);
        float2 x3 = *(const float2*)(xl + (size_t)sn3 * D + c);

        float za, zb, t0, t1, t2, t3;
        za = x0.x + xrv.x + e0.x * wev[0].x + e0.y * wev[1].x + e0.z * wev[2].x + e0.w * wev[3].x;
        zb = x0.y + xrv.y + e0.x * wev[0].y + e0.y * wev[1].y + e0.z * wev[2].y + e0.w * wev[3].y;
        za = za > 0.f ? za : 0.2f * za; zb = zb > 0.f ? zb : 0.2f * zb;
        t0 = za * atv.x + zb * atv.y;
        za = x1.x + xrv.x + e1.x * wev[0].x + e1.y * wev[1].x + e1.z * wev[2].x + e1.w * wev[3].x;
        zb = x1.y + xrv.y + e1.x * wev[0].y + e1.y * wev[1].y + e1.z * wev[2].y + e1.w * wev[3].y;
        za = za > 0.f ? za : 0.2f * za; zb = zb > 0.f ? zb : 0.2f * zb;
        t1 = za * atv.x + zb * atv.y;
        za = x2.x + xrv.x + e2.x * wev[0].x + e2.y * wev[1].x + e2.z * wev[2].x + e2.w * wev[3].x;
        zb = x2.y + xrv.y + e2.x * wev[0].y + e2.y * wev[1].y + e2.z * wev[2].y + e2.w * wev[3].y;
        za = za > 0.f ? za : 0.2f * za; zb = zb > 0.f ? zb : 0.2f * zb;
        t2 = za * atv.x + zb * atv.y;
        za = x3.x + xrv.x + e3.x * wev[0].x + e3.y * wev[1].x + e3.z * wev[2].x + e3.w * wev[3].x;
        zb = x3.y + xrv.y + e3.x * wev[0].y + e3.y * wev[1].y + e3.z * wev[2].y + e3.w * wev[3].y;
        za = za > 0.f ? za : 0.2f * za; zb = zb > 0.f ? zb : 0.2f * zb;
        t3 = za * atv.x + zb * atv.y;

        #pragma unroll
        for (int o = 16; o > 0; o >>= 1) {
            t0 += __shfl_xor_sync(0xFFFFFFFFu, t0, o);
            t1 += __shfl_xor_sync(0xFFFFFFFFu, t1, o);
            t2 += __shfl_xor_sync(0xFFFFFFFFu, t2, o);
            t3 += __shfl_xor_sync(0xFFFFFFFFu, t3, o);
        }
        float p0 = __expf(t0), p1 = __expf(t1), p2 = __expf(t2), p3 = __expf(t3);
        s0 += p0; a00 += p0 * x0.x; a01 += p0 * x0.y;
        s1 += p1; a10 += p1 * x1.x; a11 += p1 * x1.y;
        s0 += p2; a00 += p2 * x2.x; a01 += p2 * x2.y;
        s1 += p3; a10 += p3 * x3.x; a11 += p3 * x3.y;
    }
    for (; i < end; i++) {
        int sn = csr_src[i];
        float4 eav = csr_ea[i];
        float2 xv = *(const float2*)(xl + (size_t)sn * D + c);
        float z0 = xv.x + xrv.x + eav.x * wev[0].x + eav.y * wev[1].x + eav.z * wev[2].x + eav.w * wev[3].x;
        float z1 = xv.y + xrv.y + eav.x * wev[0].y + eav.y * wev[1].y + eav.z * wev[2].y + eav.w * wev[3].y;
        z0 = z0 > 0.f ? z0 : 0.2f * z0;
        z1 = z1 > 0.f ? z1 : 0.2f * z1;
        float t = z0 * atv.x + z1 * atv.y;
        #pragma unroll
        for (int o = 16; o > 0; o >>= 1) t += __shfl_xor_sync(0xFFFFFFFFu, t, o);
        float p = __expf(t);
        s0 += p; a00 += p * xv.x; a01 += p * xv.y;
    }
    float s = s0 + s1;
    float a0 = a00 + a10;
    float a1 = a01 + a11;

    float inv = 1.f / (s + 1e-16f);
    float2 bv = *(const float2*)(bias + c);
    float r0 = a0 * inv + bv.x;
    float r1 = a1 * inv + bv.y;

    int g = batch[n];
    atomicAdd(&sums[g * 64 + c], r0);
    atomicAdd(&sums[g * 64 + c + 1], r1);
    if (lane == 0) atomicAdd(&cnt[g], 1);
}

// ---------------- MLP head ----------------
__global__ void mlp_k(const float* __restrict__ sums, const int* __restrict__ cnt,
                      const float* __restrict__ mW1, const float* __restrict__ mb1,
                      const float* __restrict__ mW2, const float* __restrict__ mb2,
                      const float* __restrict__ mW3, const float* __restrict__ mb3,
                      float* __restrict__ out) {
    __shared__ float gv[64];
    __shared__ float h1[32];
    __shared__ float h2[16];
    int g = blockIdx.x, t = threadIdx.x;
    float cf = fmaxf((float)cnt[g], 1.f);
    gv[t] = sums[g * 64 + t] / cf;
    __syncthreads();
    if (t < 32) {
        float a = mb1[t];
        #pragma unroll
        for (int k = 0; k < 64; k++) a += gv[k] * mW1[k * 32 + t];
        h1[t] = fmaxf(a, 0.f);
    }
    __syncthreads();
    if (t < 16) {
        float a = mb2[t];
        #pragma unroll
        for (int k = 0; k < 32; k++) a += h1[k] * mW2[k * 16 + t];
        h2[t] = fmaxf(a, 0.f);
    }
    __syncthreads();
    if (t < 4) {
        float a = mb3[t];
        #pragma unroll
        for (int k = 0; k < 16; k++) a += h2[k] * mW3[k * 4 + t];
        out[g * 4 + t] = a;
    }
}

// ---------------- launch ----------------
extern "C" void kernel_launch(void* const* d_in, const int* in_sizes, int n_in,
                              void* d_out, int out_size) {
    (void)in_sizes; (void)n_in; (void)out_size;
    const float* x     = (const float*)d_in[0];
    const int*   ei    = (const int*)d_in[1];
    const float* ea    = (const float*)d_in[2];
    const int*   batch = (const int*)d_in[3];
    const float* Wl1 = (const float*)d_in[4],  *bl1 = (const float*)d_in[5];
    const float* Wr1 = (const float*)d_in[6],  *br1 = (const float*)d_in[7];
    const float* We1 = (const float*)d_in[8],  *att1 = (const float*)d_in[9],  *bias1 = (const float*)d_in[10];
    const float* Wl2 = (const float*)d_in[11], *bl2 = (const float*)d_in[12];
    const float* Wr2 = (const float*)d_in[13], *br2 = (const float*)d_in[14];
    const float* We2 = (const float*)d_in[15], *att2 = (const float*)d_in[16], *bias2 = (const float*)d_in[17];
    const float* Wl3 = (const float*)d_in[18], *bl3 = (const float*)d_in[19];
    const float* Wr3 = (const float*)d_in[20], *br3 = (const float*)d_in[21];
    const float* We3 = (const float*)d_in[22], *att3 = (const float*)d_in[23], *bias3 = (const float*)d_in[24];
    const float* mW1 = (const float*)d_in[25], *mb1 = (const float*)d_in[26];
    const float* mW2 = (const float*)d_in[27], *mb2 = (const float*)d_in[28];
    const float* mW3 = (const float*)d_in[29], *mb3 = (const float*)d_in[30];
    float* out = (float*)d_out;

    const int* srcp = ei;
    const int* dstp = ei + N_EDGES;

    float *xl, *xr, *sums;
    int *deg, *rowptr, *cursor, *csr_src, *cnt;
    float4* csr_ea;
    __nv_bfloat16 *ahi, *alo, *whL, *wlL, *whR, *wlR;
    cudaGetSymbolAddress((void**)&xl, g_xl);
    cudaGetSymbolAddress((void**)&xr, g_xr);
    cudaGetSymbolAddress((void**)&sums, g_sums);
    cudaGetSymbolAddress((void**)&deg, g_deg);
    cudaGetSymbolAddress((void**)&rowptr, g_rowptr);
    cudaGetSymbolAddress((void**)&cursor, g_cursor);
    cudaGetSymbolAddress((void**)&csr_src, g_csr_src);
    cudaGetSymbolAddress((void**)&csr_ea, g_csr_ea);
    cudaGetSymbolAddress((void**)&cnt, g_cnt);
    cudaGetSymbolAddress((void**)&ahi, g_ahi);
    cudaGetSymbolAddress((void**)&alo, g_alo);
    cudaGetSymbolAddress((void**)&whL, g_whL);
    cudaGetSymbolAddress((void**)&wlL, g_wlL);
    cudaGetSymbolAddress((void**)&whR, g_whR);
    cudaGetSymbolAddress((void**)&wlR, g_wlR);

    static bool attr_done = false;
    if (!attr_done) {
        cudaFuncSetAttribute(gemm_bf16_dual, cudaFuncAttributeMaxDynamicSharedMemorySize, 61440);
        attr_done = true;
    }

    // CSR by destination (shared by all 3 layers)
    zero_i32<<<(N_NODES + 255) / 256, 256>>>(deg, N_NODES);
    hist_k<<<(N_EDGES + 255) / 256, 256>>>(dstp, deg);
    scan_k<<<1, 1024>>>(deg, rowptr, cursor);
    scatter_k<<<(N_EDGES + 255) / 256, 256>>>(srcp, dstp, (const float4*)ea, cursor, csr_src, csr_ea);

    // layer-1 dual GEMM (xl + xr in one pass)
    gemm_k12_dual<<<(N_NODES + 31) / 32, 256>>>(x, Wl1, bl1, Wr1, br1, xl, xr);

    edge_agg_h4<<<2500, 256>>>(rowptr, csr_src, csr_ea, xl, xr, We1, att1, bias1, ahi, alo);

    // ---- layer 2 (256 -> 256, H=4): one dual launch for L+R ----
    splitW_dual<<<(256 * 256 + 255) / 256, 256>>>(Wl2, Wr2, whL, wlL, whR, wlR, 256, 256);
    gemm_bf16_dual<<<dim3(4, 157, 2), 256, 61440>>>(ahi, alo, whL, wlL, whR, wlR, bl2, br2,
                                                    xl, xr, N_NODES, 256, 256);
    edge_agg_h4<<<2500, 256>>>(rowptr, csr_src, csr_ea, xl, xr, We2, att2, bias2, ahi, alo);

    // ---- layer 3 (256 -> 64, H=1, no ELU), pool fused into epilogue ----
    splitW_dual<<<(256 * 64 + 255) / 256, 256>>>(Wl3, Wr3, whL, wlL, whR, wlR, 256, 64);
    gemm_bf16_dual<<<dim3(1, 157, 2), 256, 61440>>>(ahi, alo, whL, wlL, whR, wlR, bl3, br3,
                                                    xl, xr, N_NODES, 256, 64);
    zero_pool<<<(N_GRAPHS * 64 + 255) / 256, 256>>>(sums, cnt);
    edge_agg_h1_pool<<<2500, 256>>>(rowptr, csr_src, csr_ea, xl, xr, We3, att3, bias3,
                                    batch, sums, cnt);

    // ---- MLP head ----
    mlp_k<<<N_GRAPHS, 64>>>(sums, cnt, mW1, mb1, mW2, mb2, mW3, mb3, out);
}